// round 1
// baseline (speedup 1.0000x reference)
#include <cuda_runtime.h>
#include <cuda_bf16.h>
#include <cstdio>

#define N_NODES 50000
#define N_EDGES 800000
#define DIM 128

// ---------------- device scratch (static, allocation-free) ----------------
__device__ float g_hs[(size_t)N_NODES * DIM];    // norm_src-scaled features (SpMM input)
__device__ float g_agg[(size_t)N_NODES * DIM];   // SpMM accumulator
__device__ float g_norm_src[N_NODES];
__device__ float g_norm_dst[N_NODES];
__device__ int   g_deg[2 * N_NODES];             // [0,N): out-deg(src), [N,2N): in-deg(dst)

// ---------------- small prep kernels ----------------
__global__ void zero_deg_kernel() {
    int i = blockIdx.x * blockDim.x + threadIdx.x;
    if (i < 2 * N_NODES) g_deg[i] = 0;
}

__global__ void count_deg_kernel(const int* __restrict__ src, const int* __restrict__ dst) {
    int e = blockIdx.x * blockDim.x + threadIdx.x;
    if (e < N_EDGES) {
        atomicAdd(&g_deg[src[e]], 1);
        atomicAdd(&g_deg[N_NODES + dst[e]], 1);
    }
}

__global__ void norms_kernel() {
    int i = blockIdx.x * blockDim.x + threadIdx.x;
    if (i < N_NODES) {
        g_norm_src[i] = rsqrtf((float)max(g_deg[i], 1));
        g_norm_dst[i] = rsqrtf((float)max(g_deg[N_NODES + i], 1));
    }
}

// x = emb[batch] * norm_src   (one warp per node, float4 per lane)
__global__ void gather_kernel(const int* __restrict__ batch, const float* __restrict__ emb) {
    int t = blockIdx.x * blockDim.x + threadIdx.x;
    int i = t >> 5;
    int c = (t & 31) * 4;
    if (i < N_NODES) {
        int row = batch[i];
        float ns = g_norm_src[i];
        float4 v = *(const float4*)(emb + (size_t)row * DIM + c);
        v.x *= ns; v.y *= ns; v.z *= ns; v.w *= ns;
        *(float4*)(g_hs + (size_t)i * DIM + c) = v;
    }
}

// agg[dst[e]] += hs[src[e]]  (one warp per edge; vec4 fire-and-forget reductions)
__global__ void scatter_kernel(const int* __restrict__ src, const int* __restrict__ dst) {
    int t = blockIdx.x * blockDim.x + threadIdx.x;
    int e = t >> 5;
    int c = (t & 31) * 4;
    if (e < N_EDGES) {
        int s = __ldg(src + e);
        int d = __ldg(dst + e);
        float4 v = *(const float4*)(g_hs + (size_t)s * DIM + c);
        float* p = g_agg + (size_t)d * DIM + c;
        asm volatile("red.global.add.v4.f32 [%0], {%1, %2, %3, %4};"
                     :: "l"(p), "f"(v.x), "f"(v.y), "f"(v.z), "f"(v.w)
                     : "memory");
    }
}

// ---------------- fused GEMM: out = relu((agg * norm_dst) @ W + b) [* norm_src] ----
// Block: 256 threads, 64-row tile. smem: W 128x128 (64KB) + A 64x128 (32KB) + bias.
// Per thread: 8 rows x 4 cols, k chunked by 4 with float4 A loads (broadcast LDS).
#define GEMM_SMEM_BYTES ((DIM * DIM + 64 * DIM + DIM) * 4)

template <int WRITE_MODE>   // 0: write g_hs scaled by norm_src   1: write final out
__global__ __launch_bounds__(256, 2)
void gemm_kernel(const float* __restrict__ W, const float* __restrict__ b,
                 float* __restrict__ out) {
    extern __shared__ float smem[];
    float* sW = smem;                 // 128*128
    float* sA = sW + DIM * DIM;       // 64*128
    float* sB = sA + 64 * DIM;        // 128

    int tid = threadIdx.x;
    // load W (16384 floats = 4096 float4)
    for (int i = tid; i < DIM * DIM / 4; i += 256)
        ((float4*)sW)[i] = ((const float4*)W)[i];
    if (tid < DIM / 4)
        ((float4*)sB)[tid] = ((const float4*)b)[tid];

    int row0 = blockIdx.x * 64;
    // load A tile, fold norm_dst
    for (int i = tid; i < 64 * DIM / 4; i += 256) {
        int r = i >> 5;          // /(DIM/4)
        int c = i & 31;
        int gr = row0 + r;
        float4 v = make_float4(0.f, 0.f, 0.f, 0.f);
        if (gr < N_NODES) {
            v = ((const float4*)(g_agg + (size_t)gr * DIM))[c];
            float nd = g_norm_dst[gr];
            v.x *= nd; v.y *= nd; v.z *= nd; v.w *= nd;
        }
        ((float4*)sA)[i] = v;
    }
    __syncthreads();

    int warp = tid >> 5, lane = tid & 31;
    int rbase = warp * 8;
    int col = lane * 4;

    float4 acc[8];
#pragma unroll
    for (int r = 0; r < 8; r++) acc[r] = make_float4(0.f, 0.f, 0.f, 0.f);

#pragma unroll 4
    for (int k = 0; k < DIM; k += 4) {
        float4 w0 = *(const float4*)(sW + (k + 0) * DIM + col);
        float4 w1 = *(const float4*)(sW + (k + 1) * DIM + col);
        float4 w2 = *(const float4*)(sW + (k + 2) * DIM + col);
        float4 w3 = *(const float4*)(sW + (k + 3) * DIM + col);
#pragma unroll
        for (int r = 0; r < 8; r++) {
            float4 a = *(const float4*)(sA + (rbase + r) * DIM + k);  // broadcast
            acc[r].x += a.x * w0.x; acc[r].y += a.x * w0.y; acc[r].z += a.x * w0.z; acc[r].w += a.x * w0.w;
            acc[r].x += a.y * w1.x; acc[r].y += a.y * w1.y; acc[r].z += a.y * w1.z; acc[r].w += a.y * w1.w;
            acc[r].x += a.z * w2.x; acc[r].y += a.z * w2.y; acc[r].z += a.z * w2.z; acc[r].w += a.z * w2.w;
            acc[r].x += a.w * w3.x; acc[r].y += a.w * w3.y; acc[r].z += a.w * w3.z; acc[r].w += a.w * w3.w;
        }
    }

    float4 bb = *(const float4*)(sB + col);
#pragma unroll
    for (int r = 0; r < 8; r++) {
        int gr = row0 + rbase + r;
        if (gr < N_NODES) {
            float4 o;
            o.x = fmaxf(acc[r].x + bb.x, 0.f);
            o.y = fmaxf(acc[r].y + bb.y, 0.f);
            o.z = fmaxf(acc[r].z + bb.z, 0.f);
            o.w = fmaxf(acc[r].w + bb.w, 0.f);
            if (WRITE_MODE == 0) {
                float ns = g_norm_src[gr];
                o.x *= ns; o.y *= ns; o.z *= ns; o.w *= ns;
                *(float4*)(g_hs + (size_t)gr * DIM + col) = o;
            } else {
                *(float4*)(out + (size_t)gr * DIM + col) = o;
            }
        }
    }
}

// ---------------- launcher ----------------
extern "C" void kernel_launch(void* const* d_in, const int* in_sizes, int n_in,
                              void* d_out, int out_size) {
    const int*   batch = (const int*)  d_in[0];
    const int*   src   = (const int*)  d_in[1];
    const int*   dst   = (const int*)  d_in[2];
    const float* emb   = (const float*)d_in[3];
    const float* W1    = (const float*)d_in[4];
    const float* b1    = (const float*)d_in[5];
    const float* W2    = (const float*)d_in[6];
    const float* b2    = (const float*)d_in[7];
    const float* W3    = (const float*)d_in[8];
    const float* b3    = (const float*)d_in[9];
    float* out = (float*)d_out;

    (void)in_sizes; (void)n_in; (void)out_size;

    cudaFuncSetAttribute(gemm_kernel<0>, cudaFuncAttributeMaxDynamicSharedMemorySize, GEMM_SMEM_BYTES);
    cudaFuncSetAttribute(gemm_kernel<1>, cudaFuncAttributeMaxDynamicSharedMemorySize, GEMM_SMEM_BYTES);

    void* agg_ptr = nullptr;
    cudaGetSymbolAddress(&agg_ptr, g_agg);

    // degrees + norms
    zero_deg_kernel<<<(2 * N_NODES + 255) / 256, 256>>>();
    count_deg_kernel<<<(N_EDGES + 255) / 256, 256>>>(src, dst);
    norms_kernel<<<(N_NODES + 255) / 256, 256>>>();

    // x = emb[batch] * norm_src
    gather_kernel<<<(N_NODES * 32 + 255) / 256, 256>>>(batch, emb);

    const int scatter_blocks = (N_EDGES * 32 + 255) / 256;
    const int gemm_blocks = (N_NODES + 63) / 64;
    const size_t agg_bytes = (size_t)N_NODES * DIM * sizeof(float);

    // layer 1
    cudaMemsetAsync(agg_ptr, 0, agg_bytes, 0);
    scatter_kernel<<<scatter_blocks, 256>>>(src, dst);
    gemm_kernel<0><<<gemm_blocks, 256, GEMM_SMEM_BYTES>>>(W1, b1, out);

    // layer 2
    cudaMemsetAsync(agg_ptr, 0, agg_bytes, 0);
    scatter_kernel<<<scatter_blocks, 256>>>(src, dst);
    gemm_kernel<0><<<gemm_blocks, 256, GEMM_SMEM_BYTES>>>(W2, b2, out);

    // layer 3 (no norm_src on output)
    cudaMemsetAsync(agg_ptr, 0, agg_bytes, 0);
    scatter_kernel<<<scatter_blocks, 256>>>(src, dst);
    gemm_kernel<1><<<gemm_blocks, 256, GEMM_SMEM_BYTES>>>(W3, b3, out);
}

// round 3
// speedup vs baseline: 1.0362x; 1.0362x over previous
#include <cuda_runtime.h>
#include <cuda_bf16.h>
#include <cstdint>

#define N_NODES 50000
#define N_EDGES 800000
#define DIM 128

// ---------------- device scratch (static, allocation-free, zero-initialized) ----
__device__ float g_hs[(size_t)N_NODES * DIM];     // norm_src-scaled features (SpMM input)
__device__ float g_agg[(size_t)N_NODES * DIM];    // SpMM accumulator (kept zeroed by GEMM)
__device__ float g_norm_src[N_NODES];
__device__ float g_norm_dst[N_NODES];
__device__ int   g_deg[2 * N_NODES];
// W fragment images: [layer][kstep(8)][ntile(16)][img(2)][lane(32)] of uint2 (b0,b1 regs)
__device__ uint2 g_Bfrag[3 * 8 * 16 * 2 * 32];

// ---------------- small prep kernels ----------------
__global__ void zero_deg_kernel() {
    int i = blockIdx.x * blockDim.x + threadIdx.x;
    if (i < 2 * N_NODES) g_deg[i] = 0;
}
__global__ void count_deg_kernel(const int* __restrict__ src, const int* __restrict__ dst) {
    int e = blockIdx.x * blockDim.x + threadIdx.x;
    if (e < N_EDGES) {
        atomicAdd(&g_deg[src[e]], 1);
        atomicAdd(&g_deg[N_NODES + dst[e]], 1);
    }
}
__global__ void norms_kernel() {
    int i = blockIdx.x * blockDim.x + threadIdx.x;
    if (i < N_NODES) {
        g_norm_src[i] = rsqrtf((float)max(g_deg[i], 1));
        g_norm_dst[i] = rsqrtf((float)max(g_deg[N_NODES + i], 1));
    }
}
__global__ void gather_kernel(const int* __restrict__ batch, const float* __restrict__ emb) {
    int t = blockIdx.x * blockDim.x + threadIdx.x;
    int i = t >> 5;
    int c = (t & 31) * 4;
    if (i < N_NODES) {
        int row = batch[i];
        float ns = g_norm_src[i];
        float4 v = *(const float4*)(emb + (size_t)row * DIM + c);
        v.x *= ns; v.y *= ns; v.z *= ns; v.w *= ns;
        *(float4*)(g_hs + (size_t)i * DIM + c) = v;
    }
}

__device__ __forceinline__ void bf16_split(float v, __nv_bfloat16& hi, __nv_bfloat16& lo) {
    hi = __float2bfloat16_rn(v);
    lo = __float2bfloat16_rn(v - __bfloat162float(hi));
}
__device__ __forceinline__ uint32_t pack2(__nv_bfloat16 a, __nv_bfloat16 b) {
    __nv_bfloat162 p = __halves2bfloat162(a, b);   // .x = a in low 16 bits
    return *(uint32_t*)&p;
}

// Build B fragment images: B(k,n) = W[k][n]; mma .col B frag for m16n8k16:
// reg0 = halves (k=2tig, n=g), (k=2tig+1, n=g); reg1 = (k=2tig+8, g), (k=2tig+9, g)
__global__ void build_Bfrag_kernel(const float* __restrict__ W1, const float* __restrict__ W2,
                                   const float* __restrict__ W3) {
    int t = blockIdx.x * blockDim.x + threadIdx.x;
    if (t >= 3 * 8 * 16 * 32) return;
    int layer = t >> 12;
    int rem = t & 4095;
    int ks = rem >> 9;
    int nt = (rem >> 5) & 15;
    int lane = rem & 31;
    int g = lane >> 2, tig = lane & 3;
    const float* W = (layer == 0) ? W1 : (layer == 1) ? W2 : W3;
    int n = nt * 8 + g;
    int k0 = ks * 16 + 2 * tig;
    float w00 = W[(k0 + 0) * DIM + n];
    float w01 = W[(k0 + 1) * DIM + n];
    float w10 = W[(k0 + 8) * DIM + n];
    float w11 = W[(k0 + 9) * DIM + n];
    __nv_bfloat16 h00, l00, h01, l01, h10, l10, h11, l11;
    bf16_split(w00, h00, l00); bf16_split(w01, h01, l01);
    bf16_split(w10, h10, l10); bf16_split(w11, h11, l11);
    int idx = (layer * 8 + ks) * 16 + nt;
    g_Bfrag[(idx * 2 + 0) * 32 + lane] = make_uint2(pack2(h00, h01), pack2(h10, h11));
    g_Bfrag[(idx * 2 + 1) * 32 + lane] = make_uint2(pack2(l00, l01), pack2(l10, l11));
}

// agg[dst[e]] += hs[src[e]]  (one warp per edge; vec4 fire-and-forget reductions)
__global__ void scatter_kernel(const int* __restrict__ src, const int* __restrict__ dst) {
    int t = blockIdx.x * blockDim.x + threadIdx.x;
    int e = t >> 5;
    int c = (t & 31) * 4;
    if (e < N_EDGES) {
        int s = __ldg(src + e);
        int d = __ldg(dst + e);
        float4 v = *(const float4*)(g_hs + (size_t)s * DIM + c);
        float* p = g_agg + (size_t)d * DIM + c;
        asm volatile("red.global.add.v4.f32 [%0], {%1, %2, %3, %4};"
                     :: "l"(p), "f"(v.x), "f"(v.y), "f"(v.z), "f"(v.w)
                     : "memory");
    }
}

// ---------------- mma.sync bf16-split GEMM ----------------
// out = relu((agg * norm_dst) @ W + b) [* norm_src], and zeroes g_agg after reading.
// CTA: 256 threads = 8 warps in 4x2 grid. CTA tile 128x128. Warp tile 32x64.
// K loop: 8 steps of k16, 3 mma passes (hi*hi + hi*lo + lo*hi).
#define PADK 136                         // bf16 elements per smem row (128 + 8 pad)
#define A_IMG_BYTES (128 * PADK * 2)     // 34816
#define GEMM_SMEM (2 * A_IMG_BYTES)      // hi + lo images

__device__ __forceinline__ void mma_bf16(float& c0, float& c1, float& c2, float& c3,
                                         uint32_t a0, uint32_t a1, uint32_t a2, uint32_t a3,
                                         uint32_t b0, uint32_t b1) {
    asm volatile(
        "mma.sync.aligned.m16n8k16.row.col.f32.bf16.bf16.f32 "
        "{%0,%1,%2,%3}, {%4,%5,%6,%7}, {%8,%9}, {%0,%1,%2,%3};"
        : "+f"(c0), "+f"(c1), "+f"(c2), "+f"(c3)
        : "r"(a0), "r"(a1), "r"(a2), "r"(a3), "r"(b0), "r"(b1));
}

__global__ __launch_bounds__(256, 1)
void mma_gemm_kernel(const float* __restrict__ bias, const uint2* __restrict__ Bfrag,
                     float* __restrict__ outp, int write_mode) {
    extern __shared__ char smem[];
    __nv_bfloat16* sAhi = (__nv_bfloat16*)smem;
    __nv_bfloat16* sAlo = (__nv_bfloat16*)(smem + A_IMG_BYTES);

    int tid = threadIdx.x;
    int wid = tid >> 5, lane = tid & 31;
    int warp_m = wid >> 1, warp_n = wid & 1;
    int g = lane >> 2, tig = lane & 3;
    int row0 = blockIdx.x * 128;

    // ---- load A tile: fold norm_dst, split to bf16 hi/lo, zero g_agg behind us ----
    #pragma unroll
    for (int it = 0; it < 16; it++) {
        int i = tid + it * 256;           // 0..4095 float4 chunks
        int r = i >> 5, c4 = i & 31;      // row, float4-col
        int gr = row0 + r;
        float4 v = make_float4(0.f, 0.f, 0.f, 0.f);
        if (gr < N_NODES) {
            float4* ap = (float4*)(g_agg + (size_t)gr * DIM) + c4;
            v = *ap;
            *ap = make_float4(0.f, 0.f, 0.f, 0.f);   // keep agg zeroed for next layer/replay
            float nd = g_norm_dst[gr];
            v.x *= nd; v.y *= nd; v.z *= nd; v.w *= nd;
        }
        __nv_bfloat16 h0, l0, h1, l1, h2, l2, h3, l3;
        bf16_split(v.x, h0, l0); bf16_split(v.y, h1, l1);
        bf16_split(v.z, h2, l2); bf16_split(v.w, h3, l3);
        uint32_t off = (uint32_t)r * PADK + (uint32_t)c4 * 4;
        *(uint2*)(sAhi + off) = make_uint2(pack2(h0, h1), pack2(h2, h3));
        *(uint2*)(sAlo + off) = make_uint2(pack2(l0, l1), pack2(l2, l3));
    }
    __syncthreads();

    float acc[2][8][4];
    #pragma unroll
    for (int mt = 0; mt < 2; mt++)
        #pragma unroll
        for (int nt = 0; nt < 8; nt++)
            #pragma unroll
            for (int q = 0; q < 4; q++) acc[mt][nt][q] = 0.f;

    const int rbase = warp_m * 32;
    #pragma unroll
    for (int ks = 0; ks < 8; ks++) {
        int kc = ks * 16 + 2 * tig;
        // A fragments: regs {r0:(g,kc), r1:(g+8,kc), r2:(g,kc+8), r3:(g+8,kc+8)}
        uint32_t ahi[2][4], alo[2][4];
        #pragma unroll
        for (int mt = 0; mt < 2; mt++) {
            int rb = rbase + mt * 16 + g;
            const __nv_bfloat16* ph = sAhi + (uint32_t)rb * PADK + kc;
            const __nv_bfloat16* pl = sAlo + (uint32_t)rb * PADK + kc;
            ahi[mt][0] = *(const uint32_t*)(ph);
            ahi[mt][1] = *(const uint32_t*)(ph + 8 * PADK);
            ahi[mt][2] = *(const uint32_t*)(ph + 8);
            ahi[mt][3] = *(const uint32_t*)(ph + 8 * PADK + 8);
            alo[mt][0] = *(const uint32_t*)(pl);
            alo[mt][1] = *(const uint32_t*)(pl + 8 * PADK);
            alo[mt][2] = *(const uint32_t*)(pl + 8);
            alo[mt][3] = *(const uint32_t*)(pl + 8 * PADK + 8);
        }
        // B fragments + MMA, 4 n-tiles at a time (register pressure)
        #pragma unroll
        for (int h = 0; h < 2; h++) {
            uint2 bh[4], bl[4];
            #pragma unroll
            for (int j = 0; j < 4; j++) {
                int ntg = warp_n * 8 + h * 4 + j;
                const uint2* bp = Bfrag + ((size_t)(ks * 16 + ntg) * 2) * 32 + lane;
                bh[j] = __ldg(bp);
                bl[j] = __ldg(bp + 32);
            }
            #pragma unroll
            for (int j = 0; j < 4; j++) {
                int nt = h * 4 + j;
                #pragma unroll
                for (int mt = 0; mt < 2; mt++) {
                    float* c = acc[mt][nt];
                    mma_bf16(c[0], c[1], c[2], c[3],
                             ahi[mt][0], ahi[mt][1], ahi[mt][2], ahi[mt][3], bh[j].x, bh[j].y);
                    mma_bf16(c[0], c[1], c[2], c[3],
                             ahi[mt][0], ahi[mt][1], ahi[mt][2], ahi[mt][3], bl[j].x, bl[j].y);
                    mma_bf16(c[0], c[1], c[2], c[3],
                             alo[mt][0], alo[mt][1], alo[mt][2], alo[mt][3], bh[j].x, bh[j].y);
                }
            }
        }
    }

    // ---- epilogue: bias + relu (+ norm_src fold), write float2 pairs ----
    #pragma unroll
    for (int mt = 0; mt < 2; mt++) {
        int ra = row0 + rbase + mt * 16 + g;   // rows ra, ra+8
        int rb = ra + 8;
        bool va = ra < N_NODES, vb = rb < N_NODES;
        float nsa = 1.f, nsb = 1.f;
        float* da;
        float* db;
        if (write_mode == 0) {
            if (va) nsa = g_norm_src[ra];
            if (vb) nsb = g_norm_src[rb];
            da = g_hs + (size_t)ra * DIM;
            db = g_hs + (size_t)rb * DIM;
        } else {
            da = outp + (size_t)ra * DIM;
            db = outp + (size_t)rb * DIM;
        }
        #pragma unroll
        for (int nt = 0; nt < 8; nt++) {
            int col = warp_n * 64 + nt * 8 + 2 * tig;
            float2 b2 = __ldg((const float2*)(bias + col));
            float* c = acc[mt][nt];
            if (va) {
                float2 o;
                o.x = fmaxf(c[0] + b2.x, 0.f) * nsa;
                o.y = fmaxf(c[1] + b2.y, 0.f) * nsa;
                *(float2*)(da + col) = o;
            }
            if (vb) {
                float2 o;
                o.x = fmaxf(c[2] + b2.x, 0.f) * nsb;
                o.y = fmaxf(c[3] + b2.y, 0.f) * nsb;
                *(float2*)(db + col) = o;
            }
        }
    }
}

// ---------------- launcher ----------------
extern "C" void kernel_launch(void* const* d_in, const int* in_sizes, int n_in,
                              void* d_out, int out_size) {
    const int*   batch = (const int*)  d_in[0];
    const int*   src   = (const int*)  d_in[1];
    const int*   dst   = (const int*)  d_in[2];
    const float* emb   = (const float*)d_in[3];
    const float* W1    = (const float*)d_in[4];
    const float* b1    = (const float*)d_in[5];
    const float* W2    = (const float*)d_in[6];
    const float* b2    = (const float*)d_in[7];
    const float* W3    = (const float*)d_in[8];
    const float* b3    = (const float*)d_in[9];
    float* out = (float*)d_out;
    (void)in_sizes; (void)n_in; (void)out_size;

    cudaFuncSetAttribute(mma_gemm_kernel, cudaFuncAttributeMaxDynamicSharedMemorySize, GEMM_SMEM);

    void* bf_ptr = nullptr;
    cudaGetSymbolAddress(&bf_ptr, g_Bfrag);
    const uint2* Bf = (const uint2*)bf_ptr;
    const size_t BF_LAYER = 8 * 16 * 2 * 32;   // uint2 entries per layer

    // degrees + norms + W fragment images
    zero_deg_kernel<<<(2 * N_NODES + 255) / 256, 256>>>();
    count_deg_kernel<<<(N_EDGES + 255) / 256, 256>>>(src, dst);
    norms_kernel<<<(N_NODES + 255) / 256, 256>>>();
    build_Bfrag_kernel<<<(3 * 8 * 16 * 32 + 255) / 256, 256>>>(W1, W2, W3);

    // x = emb[batch] * norm_src
    gather_kernel<<<(N_NODES * 32 + 255) / 256, 256>>>(batch, emb);

    const int scatter_blocks = (N_EDGES * 32 + 255) / 256;
    const int gemm_blocks = (N_NODES + 127) / 128;

    // layer 1  (g_agg is zero: zero-initialized at load, re-zeroed by every GEMM)
    scatter_kernel<<<scatter_blocks, 256>>>(src, dst);
    mma_gemm_kernel<<<gemm_blocks, 256, GEMM_SMEM>>>(b1, Bf + 0 * BF_LAYER, out, 0);

    // layer 2
    scatter_kernel<<<scatter_blocks, 256>>>(src, dst);
    mma_gemm_kernel<<<gemm_blocks, 256, GEMM_SMEM>>>(b2, Bf + 1 * BF_LAYER, out, 0);

    // layer 3 (final output, no norm_src fold)
    scatter_kernel<<<scatter_blocks, 256>>>(src, dst);
    mma_gemm_kernel<<<gemm_blocks, 256, GEMM_SMEM>>>(b3, Bf + 2 * BF_LAYER, out, 1);
}

// round 7
// speedup vs baseline: 1.2459x; 1.2024x over previous
#include <cuda_runtime.h>
#include <cuda_bf16.h>
#include <cstdint>

#define N_NODES 50000
#define N_EDGES 800000
#define DIM 128
#define SCAN_BLK 512
#define NB ((N_NODES + SCAN_BLK - 1) / SCAN_BLK)   // 98

// ---------------- device scratch (static, allocation-free, zero-initialized) ----
__device__ float g_hs[(size_t)N_NODES * DIM];     // feature ping buffer
__device__ float g_hs2[(size_t)N_NODES * DIM];    // feature pong buffer
__device__ float g_norm_src[N_NODES];
__device__ float g_norm_dst[N_NODES];
__device__ int   g_deg[2 * N_NODES];              // [0,N) out-deg, [N,2N) in-deg
__device__ int   g_row_ptr[N_NODES + 1];          // CSR by dst
__device__ int   g_cursor[N_NODES];
__device__ int   g_blocksum[NB];
__device__ int   g_csr_src[N_EDGES];
// W fragment images: [layer][kstep(8)][ntile(16)][img(2)][lane(32)] of uint2
__device__ uint2 g_Bfrag[3 * 8 * 16 * 2 * 32];

// ---------------- prep kernels ----------------
__global__ void zero_deg_kernel() {
    int i = blockIdx.x * blockDim.x + threadIdx.x;
    if (i < 2 * N_NODES) g_deg[i] = 0;
}
__global__ void count_deg_kernel(const int* __restrict__ src, const int* __restrict__ dst) {
    int e = blockIdx.x * blockDim.x + threadIdx.x;
    if (e < N_EDGES) {
        atomicAdd(&g_deg[src[e]], 1);
        atomicAdd(&g_deg[N_NODES + dst[e]], 1);
    }
}
__global__ void norms_kernel() {
    int i = blockIdx.x * blockDim.x + threadIdx.x;
    if (i < N_NODES) {
        g_norm_src[i] = rsqrtf((float)max(g_deg[i], 1));
        g_norm_dst[i] = rsqrtf((float)max(g_deg[N_NODES + i], 1));
    }
}

// ---- CSR build: block scan of in-degrees -> row_ptr; atomic-cursor fill ----
__global__ void scan_block_kernel() {
    __shared__ int sdata[SCAN_BLK];
    int i = blockIdx.x * SCAN_BLK + threadIdx.x;
    int v = (i < N_NODES) ? g_deg[N_NODES + i] : 0;
    sdata[threadIdx.x] = v;
    __syncthreads();
    for (int off = 1; off < SCAN_BLK; off <<= 1) {
        int t = (threadIdx.x >= off) ? sdata[threadIdx.x - off] : 0;
        __syncthreads();
        sdata[threadIdx.x] += t;
        __syncthreads();
    }
    if (i < N_NODES) g_row_ptr[i + 1] = sdata[threadIdx.x];
    if (threadIdx.x == SCAN_BLK - 1) g_blocksum[blockIdx.x] = sdata[SCAN_BLK - 1];
}
__global__ void scan_tops_kernel() {
    if (threadIdx.x == 0) {
        int acc = 0;
        for (int b = 0; b < NB; b++) { int t = g_blocksum[b]; g_blocksum[b] = acc; acc += t; }
    }
}
__global__ void scan_add_kernel() {
    int i = blockIdx.x * SCAN_BLK + threadIdx.x;
    if (i < N_NODES) g_row_ptr[i + 1] += g_blocksum[i >> 9];
    if (i == 0) g_row_ptr[0] = 0;
}
__global__ void cursor_kernel() {
    int i = blockIdx.x * blockDim.x + threadIdx.x;
    if (i < N_NODES) g_cursor[i] = g_row_ptr[i];
}
__global__ void fill_csr_kernel(const int* __restrict__ src, const int* __restrict__ dst) {
    int e = blockIdx.x * blockDim.x + threadIdx.x;
    if (e < N_EDGES) {
        int pos = atomicAdd(&g_cursor[dst[e]], 1);
        g_csr_src[pos] = src[e];
    }
}

// x = emb[batch] * norm_src   -> g_hs
__global__ void gather_kernel(const int* __restrict__ batch, const float* __restrict__ emb) {
    int t = blockIdx.x * blockDim.x + threadIdx.x;
    int i = t >> 5;
    int c = (t & 31) * 4;
    if (i < N_NODES) {
        int row = batch[i];
        float ns = g_norm_src[i];
        float4 v = *(const float4*)(emb + (size_t)row * DIM + c);
        v.x *= ns; v.y *= ns; v.z *= ns; v.w *= ns;
        *(float4*)(g_hs + (size_t)i * DIM + c) = v;
    }
}

__device__ __forceinline__ void bf16_split(float v, __nv_bfloat16& hi, __nv_bfloat16& lo) {
    hi = __float2bfloat16_rn(v);
    lo = __float2bfloat16_rn(v - __bfloat162float(hi));
}
__device__ __forceinline__ uint32_t pack2(__nv_bfloat16 a, __nv_bfloat16 b) {
    __nv_bfloat162 p = __halves2bfloat162(a, b);
    return *(uint32_t*)&p;
}

// B fragment images for mma.m16n8k16 .col B
__global__ void build_Bfrag_kernel(const float* __restrict__ W1, const float* __restrict__ W2,
                                   const float* __restrict__ W3) {
    int t = blockIdx.x * blockDim.x + threadIdx.x;
    if (t >= 3 * 8 * 16 * 32) return;
    int layer = t >> 12;
    int rem = t & 4095;
    int ks = rem >> 9;
    int nt = (rem >> 5) & 15;
    int lane = rem & 31;
    int g = lane >> 2, tig = lane & 3;
    const float* W = (layer == 0) ? W1 : (layer == 1) ? W2 : W3;
    int n = nt * 8 + g;
    int k0 = ks * 16 + 2 * tig;
    float w00 = W[(k0 + 0) * DIM + n];
    float w01 = W[(k0 + 1) * DIM + n];
    float w10 = W[(k0 + 8) * DIM + n];
    float w11 = W[(k0 + 9) * DIM + n];
    __nv_bfloat16 h00, l00, h01, l01, h10, l10, h11, l11;
    bf16_split(w00, h00, l00); bf16_split(w01, h01, l01);
    bf16_split(w10, h10, l10); bf16_split(w11, h11, l11);
    int idx = (layer * 8 + ks) * 16 + nt;
    g_Bfrag[(idx * 2 + 0) * 32 + lane] = make_uint2(pack2(h00, h01), pack2(h10, h11));
    g_Bfrag[(idx * 2 + 1) * 32 + lane] = make_uint2(pack2(l00, l01), pack2(l10, l11));
}

// ---------------- fused aggregate + bf16-split mma GEMM ----------------
// Reads hin (read-only this layer), writes hout (or final out).
#define PADK 136
#define A_IMG_BYTES (128 * PADK * 2)
#define GEMM_SMEM (2 * A_IMG_BYTES)

__device__ __forceinline__ void mma_bf16(float& c0, float& c1, float& c2, float& c3,
                                         uint32_t a0, uint32_t a1, uint32_t a2, uint32_t a3,
                                         uint32_t b0, uint32_t b1) {
    asm volatile(
        "mma.sync.aligned.m16n8k16.row.col.f32.bf16.bf16.f32 "
        "{%0,%1,%2,%3}, {%4,%5,%6,%7}, {%8,%9}, {%0,%1,%2,%3};"
        : "+f"(c0), "+f"(c1), "+f"(c2), "+f"(c3)
        : "r"(a0), "r"(a1), "r"(a2), "r"(a3), "r"(b0), "r"(b1));
}

__global__ __launch_bounds__(256, 1)
void fused_gcn_kernel(const float* __restrict__ hin, float* __restrict__ hout,
                      const float* __restrict__ bias, const uint2* __restrict__ Bfrag,
                      int write_mode) {
    extern __shared__ char smem[];
    __nv_bfloat16* sAhi = (__nv_bfloat16*)smem;
    __nv_bfloat16* sAlo = (__nv_bfloat16*)(smem + A_IMG_BYTES);

    int tid = threadIdx.x;
    int wid = tid >> 5, lane = tid & 31;
    int warp_m = wid >> 1, warp_n = wid & 1;
    int g = lane >> 2, tig = lane & 3;
    int row0 = blockIdx.x * 128;

    // ---- phase 1: aggregate 16 rows per warp (CSR segment sum of hin[src]),
    //      4-deep software pipeline over edges for MLP ----
    #pragma unroll 1
    for (int rr = 0; rr < 16; rr++) {
        int r = wid * 16 + rr;
        int gr = row0 + r;
        float ax = 0.f, ay = 0.f, az = 0.f, aw = 0.f;
        if (gr < N_NODES) {
            int beg = g_row_ptr[gr];
            int end = g_row_ptr[gr + 1];
            int j = beg;
            // 4-wide main loop: 4 independent row loads in flight
            for (; j + 3 < end; j += 4) {
                int s0 = __ldg(g_csr_src + j);
                int s1 = __ldg(g_csr_src + j + 1);
                int s2 = __ldg(g_csr_src + j + 2);
                int s3 = __ldg(g_csr_src + j + 3);
                float4 v0 = __ldg((const float4*)(hin + (size_t)s0 * DIM) + lane);
                float4 v1 = __ldg((const float4*)(hin + (size_t)s1 * DIM) + lane);
                float4 v2 = __ldg((const float4*)(hin + (size_t)s2 * DIM) + lane);
                float4 v3 = __ldg((const float4*)(hin + (size_t)s3 * DIM) + lane);
                ax += v0.x; ay += v0.y; az += v0.z; aw += v0.w;
                ax += v1.x; ay += v1.y; az += v1.z; aw += v1.w;
                ax += v2.x; ay += v2.y; az += v2.z; aw += v2.w;
                ax += v3.x; ay += v3.y; az += v3.z; aw += v3.w;
            }
            for (; j < end; j++) {
                int s0 = __ldg(g_csr_src + j);
                float4 v0 = __ldg((const float4*)(hin + (size_t)s0 * DIM) + lane);
                ax += v0.x; ay += v0.y; az += v0.z; aw += v0.w;
            }
            float nd = g_norm_dst[gr];
            ax *= nd; ay *= nd; az *= nd; aw *= nd;
        }
        __nv_bfloat16 h0, l0, h1, l1, h2, l2, h3, l3;
        bf16_split(ax, h0, l0); bf16_split(ay, h1, l1);
        bf16_split(az, h2, l2); bf16_split(aw, h3, l3);
        uint32_t off = (uint32_t)r * PADK + (uint32_t)lane * 4;
        *(uint2*)(sAhi + off) = make_uint2(pack2(h0, h1), pack2(h2, h3));
        *(uint2*)(sAlo + off) = make_uint2(pack2(l0, l1), pack2(l2, l3));
    }
    __syncthreads();

    // ---- phase 2: MMA ----
    float acc[2][8][4];
    #pragma unroll
    for (int mt = 0; mt < 2; mt++)
        #pragma unroll
        for (int nt = 0; nt < 8; nt++)
            #pragma unroll
            for (int q = 0; q < 4; q++) acc[mt][nt][q] = 0.f;

    const int rbase = warp_m * 32;
    #pragma unroll
    for (int ks = 0; ks < 8; ks++) {
        int kc = ks * 16 + 2 * tig;
        uint32_t ahi[2][4], alo[2][4];
        #pragma unroll
        for (int mt = 0; mt < 2; mt++) {
            int rb = rbase + mt * 16 + g;
            const __nv_bfloat16* ph = sAhi + (uint32_t)rb * PADK + kc;
            const __nv_bfloat16* pl = sAlo + (uint32_t)rb * PADK + kc;
            ahi[mt][0] = *(const uint32_t*)(ph);
            ahi[mt][1] = *(const uint32_t*)(ph + 8 * PADK);
            ahi[mt][2] = *(const uint32_t*)(ph + 8);
            ahi[mt][3] = *(const uint32_t*)(ph + 8 * PADK + 8);
            alo[mt][0] = *(const uint32_t*)(pl);
            alo[mt][1] = *(const uint32_t*)(pl + 8 * PADK);
            alo[mt][2] = *(const uint32_t*)(pl + 8);
            alo[mt][3] = *(const uint32_t*)(pl + 8 * PADK + 8);
        }
        #pragma unroll
        for (int h = 0; h < 2; h++) {
            uint2 bh[4], bl[4];
            #pragma unroll
            for (int j = 0; j < 4; j++) {
                int ntg = warp_n * 8 + h * 4 + j;
                const uint2* bp = Bfrag + ((size_t)(ks * 16 + ntg) * 2) * 32 + lane;
                bh[j] = __ldg(bp);
                bl[j] = __ldg(bp + 32);
            }
            #pragma unroll
            for (int j = 0; j < 4; j++) {
                int nt = h * 4 + j;
                #pragma unroll
                for (int mt = 0; mt < 2; mt++) {
                    float* c = acc[mt][nt];
                    mma_bf16(c[0], c[1], c[2], c[3],
                             ahi[mt][0], ahi[mt][1], ahi[mt][2], ahi[mt][3], bh[j].x, bh[j].y);
                    mma_bf16(c[0], c[1], c[2], c[3],
                             ahi[mt][0], ahi[mt][1], ahi[mt][2], ahi[mt][3], bl[j].x, bl[j].y);
                    mma_bf16(c[0], c[1], c[2], c[3],
                             alo[mt][0], alo[mt][1], alo[mt][2], alo[mt][3], bh[j].x, bh[j].y);
                }
            }
        }
    }

    // ---- epilogue: bias + relu (+ norm_src fold), write hout ----
    #pragma unroll
    for (int mt = 0; mt < 2; mt++) {
        int ra = row0 + rbase + mt * 16 + g;
        int rb = ra + 8;
        bool va = ra < N_NODES, vb = rb < N_NODES;
        float nsa = 1.f, nsb = 1.f;
        if (write_mode == 0) {
            if (va) nsa = g_norm_src[ra];
            if (vb) nsb = g_norm_src[rb];
        }
        float* da = hout + (size_t)ra * DIM;
        float* db = hout + (size_t)rb * DIM;
        #pragma unroll
        for (int nt = 0; nt < 8; nt++) {
            int col = warp_n * 64 + nt * 8 + 2 * tig;
            float2 b2 = __ldg((const float2*)(bias + col));
            float* c = acc[mt][nt];
            if (va) {
                float2 o;
                o.x = fmaxf(c[0] + b2.x, 0.f) * nsa;
                o.y = fmaxf(c[1] + b2.y, 0.f) * nsa;
                *(float2*)(da + col) = o;
            }
            if (vb) {
                float2 o;
                o.x = fmaxf(c[2] + b2.x, 0.f) * nsb;
                o.y = fmaxf(c[3] + b2.y, 0.f) * nsb;
                *(float2*)(db + col) = o;
            }
        }
    }
}

// ---------------- launcher ----------------
extern "C" void kernel_launch(void* const* d_in, const int* in_sizes, int n_in,
                              void* d_out, int out_size) {
    const int*   batch = (const int*)  d_in[0];
    const int*   src   = (const int*)  d_in[1];
    const int*   dst   = (const int*)  d_in[2];
    const float* emb   = (const float*)d_in[3];
    const float* W1    = (const float*)d_in[4];
    const float* b1    = (const float*)d_in[5];
    const float* W2    = (const float*)d_in[6];
    const float* b2    = (const float*)d_in[7];
    const float* W3    = (const float*)d_in[8];
    const float* b3    = (const float*)d_in[9];
    float* out = (float*)d_out;
    (void)in_sizes; (void)n_in; (void)out_size;

    cudaFuncSetAttribute(fused_gcn_kernel, cudaFuncAttributeMaxDynamicSharedMemorySize, GEMM_SMEM);

    void* bf_ptr = nullptr;  cudaGetSymbolAddress(&bf_ptr, g_Bfrag);
    void* hs_ptr = nullptr;  cudaGetSymbolAddress(&hs_ptr, g_hs);
    void* hs2_ptr = nullptr; cudaGetSymbolAddress(&hs2_ptr, g_hs2);
    const uint2* Bf = (const uint2*)bf_ptr;
    float* hs  = (float*)hs_ptr;
    float* hs2 = (float*)hs2_ptr;
    const size_t BF_LAYER = 8 * 16 * 2 * 32;

    // degrees + norms + W fragment images
    zero_deg_kernel<<<(2 * N_NODES + 255) / 256, 256>>>();
    count_deg_kernel<<<(N_EDGES + 255) / 256, 256>>>(src, dst);
    norms_kernel<<<(N_NODES + 255) / 256, 256>>>();
    build_Bfrag_kernel<<<(3 * 8 * 16 * 32 + 255) / 256, 256>>>(W1, W2, W3);

    // CSR by dst
    scan_block_kernel<<<NB, SCAN_BLK>>>();
    scan_tops_kernel<<<1, 32>>>();
    scan_add_kernel<<<NB, SCAN_BLK>>>();
    cursor_kernel<<<(N_NODES + 255) / 256, 256>>>();
    fill_csr_kernel<<<(N_EDGES + 255) / 256, 256>>>(src, dst);

    // x = emb[batch] * norm_src -> hs
    gather_kernel<<<(N_NODES * 32 + 255) / 256, 256>>>(batch, emb);

    const int gemm_blocks = (N_NODES + 127) / 128;
    // ping-pong buffers: hs -> hs2 -> hs -> out
    fused_gcn_kernel<<<gemm_blocks, 256, GEMM_SMEM>>>(hs,  hs2, b1, Bf + 0 * BF_LAYER, 0);
    fused_gcn_kernel<<<gemm_blocks, 256, GEMM_SMEM>>>(hs2, hs,  b2, Bf + 1 * BF_LAYER, 0);
    fused_gcn_kernel<<<gemm_blocks, 256, GEMM_SMEM>>>(hs,  out, b3, Bf + 2 * BF_LAYER, 1);
}

// round 8
// speedup vs baseline: 2.2800x; 1.8300x over previous
#include <cuda_runtime.h>
#include <cuda_bf16.h>
#include <cstdint>

#define N_NODES 50000
#define N_EDGES 800000
#define DIM 128
#define SCAN_BLK 512
#define NB ((N_NODES + SCAN_BLK - 1) / SCAN_BLK)   // 98

// ---------------- device scratch (static, allocation-free, zero-initialized) ----
__device__ float g_hs[(size_t)N_NODES * DIM];     // feature ping buffer
__device__ float g_hs2[(size_t)N_NODES * DIM];    // feature pong buffer
__device__ float g_agg[(size_t)N_NODES * DIM];    // normalized aggregate (agg * norm_dst)
__device__ float g_norm_src[N_NODES];
__device__ float g_norm_dst[N_NODES];
__device__ int   g_deg[2 * N_NODES];              // [0,N) out-deg, [N,2N) in-deg
__device__ int   g_row_ptr[N_NODES + 1];          // CSR by dst
__device__ int   g_cursor[N_NODES];
__device__ int   g_blocksum[NB];
__device__ int   g_csr_src[N_EDGES];
// W fragment images: [layer][kstep(8)][ntile(16)][img(2)][lane(32)] of uint2
__device__ uint2 g_Bfrag[3 * 8 * 16 * 2 * 32];

// ---------------- prep kernels ----------------
__global__ void zero_deg_kernel() {
    int i = blockIdx.x * blockDim.x + threadIdx.x;
    if (i < 2 * N_NODES) g_deg[i] = 0;
}
__global__ void count_deg_kernel(const int* __restrict__ src, const int* __restrict__ dst) {
    int e = blockIdx.x * blockDim.x + threadIdx.x;
    if (e < N_EDGES) {
        atomicAdd(&g_deg[src[e]], 1);
        atomicAdd(&g_deg[N_NODES + dst[e]], 1);
    }
}
__global__ void norms_kernel() {
    int i = blockIdx.x * blockDim.x + threadIdx.x;
    if (i < N_NODES) {
        g_norm_src[i] = rsqrtf((float)max(g_deg[i], 1));
        g_norm_dst[i] = rsqrtf((float)max(g_deg[N_NODES + i], 1));
    }
}

// ---- CSR build: block scan of in-degrees -> row_ptr; atomic-cursor fill ----
__global__ void scan_block_kernel() {
    __shared__ int sdata[SCAN_BLK];
    int i = blockIdx.x * SCAN_BLK + threadIdx.x;
    int v = (i < N_NODES) ? g_deg[N_NODES + i] : 0;
    sdata[threadIdx.x] = v;
    __syncthreads();
    for (int off = 1; off < SCAN_BLK; off <<= 1) {
        int t = (threadIdx.x >= off) ? sdata[threadIdx.x - off] : 0;
        __syncthreads();
        sdata[threadIdx.x] += t;
        __syncthreads();
    }
    if (i < N_NODES) g_row_ptr[i + 1] = sdata[threadIdx.x];
    if (threadIdx.x == SCAN_BLK - 1) g_blocksum[blockIdx.x] = sdata[SCAN_BLK - 1];
}
__global__ void scan_tops_kernel() {
    if (threadIdx.x == 0) {
        int acc = 0;
        for (int b = 0; b < NB; b++) { int t = g_blocksum[b]; g_blocksum[b] = acc; acc += t; }
    }
}
__global__ void scan_add_kernel() {
    int i = blockIdx.x * SCAN_BLK + threadIdx.x;
    if (i < N_NODES) g_row_ptr[i + 1] += g_blocksum[i >> 9];
    if (i == 0) g_row_ptr[0] = 0;
}
__global__ void cursor_kernel() {
    int i = blockIdx.x * blockDim.x + threadIdx.x;
    if (i < N_NODES) g_cursor[i] = g_row_ptr[i];
}
__global__ void fill_csr_kernel(const int* __restrict__ src, const int* __restrict__ dst) {
    int e = blockIdx.x * blockDim.x + threadIdx.x;
    if (e < N_EDGES) {
        int pos = atomicAdd(&g_cursor[dst[e]], 1);
        g_csr_src[pos] = src[e];
    }
}

// x = emb[batch] * norm_src   -> g_hs
__global__ void gather_kernel(const int* __restrict__ batch, const float* __restrict__ emb) {
    int t = blockIdx.x * blockDim.x + threadIdx.x;
    int i = t >> 5;
    int c = (t & 31) * 4;
    if (i < N_NODES) {
        int row = batch[i];
        float ns = g_norm_src[i];
        float4 v = *(const float4*)(emb + (size_t)row * DIM + c);
        v.x *= ns; v.y *= ns; v.z *= ns; v.w *= ns;
        *(float4*)(g_hs + (size_t)i * DIM + c) = v;
    }
}

__device__ __forceinline__ void bf16_split(float v, __nv_bfloat16& hi, __nv_bfloat16& lo) {
    hi = __float2bfloat16_rn(v);
    lo = __float2bfloat16_rn(v - __bfloat162float(hi));
}
__device__ __forceinline__ uint32_t pack2(__nv_bfloat16 a, __nv_bfloat16 b) {
    __nv_bfloat162 p = __halves2bfloat162(a, b);
    return *(uint32_t*)&p;
}

// B fragment images for mma.m16n8k16 .col B
__global__ void build_Bfrag_kernel(const float* __restrict__ W1, const float* __restrict__ W2,
                                   const float* __restrict__ W3) {
    int t = blockIdx.x * blockDim.x + threadIdx.x;
    if (t >= 3 * 8 * 16 * 32) return;
    int layer = t >> 12;
    int rem = t & 4095;
    int ks = rem >> 9;
    int nt = (rem >> 5) & 15;
    int lane = rem & 31;
    int g = lane >> 2, tig = lane & 3;
    const float* W = (layer == 0) ? W1 : (layer == 1) ? W2 : W3;
    int n = nt * 8 + g;
    int k0 = ks * 16 + 2 * tig;
    float w00 = W[(k0 + 0) * DIM + n];
    float w01 = W[(k0 + 1) * DIM + n];
    float w10 = W[(k0 + 8) * DIM + n];
    float w11 = W[(k0 + 9) * DIM + n];
    __nv_bfloat16 h00, l00, h01, l01, h10, l10, h11, l11;
    bf16_split(w00, h00, l00); bf16_split(w01, h01, l01);
    bf16_split(w10, h10, l10); bf16_split(w11, h11, l11);
    int idx = (layer * 8 + ks) * 16 + nt;
    g_Bfrag[(idx * 2 + 0) * 32 + lane] = make_uint2(pack2(h00, h01), pack2(h10, h11));
    g_Bfrag[(idx * 2 + 1) * 32 + lane] = make_uint2(pack2(l00, l01), pack2(l10, l11));
}

// ---------------- aggregation: g_agg[r] = norm_dst[r] * sum_{e in CSR[r]} hin[src[e]] ----
// Warp per row, lane owns one float4 column slice. Low regs, no smem -> high occupancy.
__global__ __launch_bounds__(256)
void aggregate_kernel(const float* __restrict__ hin) {
    int t = blockIdx.x * blockDim.x + threadIdx.x;
    int gr = t >> 5;
    int lane = t & 31;
    if (gr >= N_NODES) return;

    int beg = __ldg(g_row_ptr + gr);
    int end = __ldg(g_row_ptr + gr + 1);
    float ax = 0.f, ay = 0.f, az = 0.f, aw = 0.f;
    int j = beg;
    for (; j + 3 < end; j += 4) {
        int s0 = __ldg(g_csr_src + j);
        int s1 = __ldg(g_csr_src + j + 1);
        int s2 = __ldg(g_csr_src + j + 2);
        int s3 = __ldg(g_csr_src + j + 3);
        float4 v0 = __ldg((const float4*)(hin + (size_t)s0 * DIM) + lane);
        float4 v1 = __ldg((const float4*)(hin + (size_t)s1 * DIM) + lane);
        float4 v2 = __ldg((const float4*)(hin + (size_t)s2 * DIM) + lane);
        float4 v3 = __ldg((const float4*)(hin + (size_t)s3 * DIM) + lane);
        ax += v0.x; ay += v0.y; az += v0.z; aw += v0.w;
        ax += v1.x; ay += v1.y; az += v1.z; aw += v1.w;
        ax += v2.x; ay += v2.y; az += v2.z; aw += v2.w;
        ax += v3.x; ay += v3.y; az += v3.z; aw += v3.w;
    }
    for (; j < end; j++) {
        int s0 = __ldg(g_csr_src + j);
        float4 v0 = __ldg((const float4*)(hin + (size_t)s0 * DIM) + lane);
        ax += v0.x; ay += v0.y; az += v0.z; aw += v0.w;
    }
    float nd = __ldg(g_norm_dst + gr);
    ((float4*)(g_agg + (size_t)gr * DIM))[lane] = make_float4(ax * nd, ay * nd, az * nd, aw * nd);
}

// ---------------- bf16-split mma GEMM: hout = relu(g_agg @ W + b) [* norm_src] ----
#define PADK 136
#define A_IMG_BYTES (128 * PADK * 2)
#define GEMM_SMEM (2 * A_IMG_BYTES)

__device__ __forceinline__ void mma_bf16(float& c0, float& c1, float& c2, float& c3,
                                         uint32_t a0, uint32_t a1, uint32_t a2, uint32_t a3,
                                         uint32_t b0, uint32_t b1) {
    asm volatile(
        "mma.sync.aligned.m16n8k16.row.col.f32.bf16.bf16.f32 "
        "{%0,%1,%2,%3}, {%4,%5,%6,%7}, {%8,%9}, {%0,%1,%2,%3};"
        : "+f"(c0), "+f"(c1), "+f"(c2), "+f"(c3)
        : "r"(a0), "r"(a1), "r"(a2), "r"(a3), "r"(b0), "r"(b1));
}

__global__ __launch_bounds__(256, 1)
void mma_gemm_kernel(float* __restrict__ hout, const float* __restrict__ bias,
                     const uint2* __restrict__ Bfrag, int write_mode) {
    extern __shared__ char smem[];
    __nv_bfloat16* sAhi = (__nv_bfloat16*)smem;
    __nv_bfloat16* sAlo = (__nv_bfloat16*)(smem + A_IMG_BYTES);

    int tid = threadIdx.x;
    int wid = tid >> 5, lane = tid & 31;
    int warp_m = wid >> 1, warp_n = wid & 1;
    int g = lane >> 2, tig = lane & 3;
    int row0 = blockIdx.x * 128;

    // ---- load A tile (coalesced stream from g_agg), bf16 split into smem ----
    #pragma unroll
    for (int it = 0; it < 16; it++) {
        int i = tid + it * 256;           // 0..4095 float4 chunks
        int r = i >> 5, c4 = i & 31;
        int gr = row0 + r;
        float4 v = make_float4(0.f, 0.f, 0.f, 0.f);
        if (gr < N_NODES)
            v = ((const float4*)(g_agg + (size_t)gr * DIM))[c4];
        __nv_bfloat16 h0, l0, h1, l1, h2, l2, h3, l3;
        bf16_split(v.x, h0, l0); bf16_split(v.y, h1, l1);
        bf16_split(v.z, h2, l2); bf16_split(v.w, h3, l3);
        uint32_t off = (uint32_t)r * PADK + (uint32_t)c4 * 4;
        *(uint2*)(sAhi + off) = make_uint2(pack2(h0, h1), pack2(h2, h3));
        *(uint2*)(sAlo + off) = make_uint2(pack2(l0, l1), pack2(l2, l3));
    }
    __syncthreads();

    // ---- MMA ----
    float acc[2][8][4];
    #pragma unroll
    for (int mt = 0; mt < 2; mt++)
        #pragma unroll
        for (int nt = 0; nt < 8; nt++)
            #pragma unroll
            for (int q = 0; q < 4; q++) acc[mt][nt][q] = 0.f;

    const int rbase = warp_m * 32;
    #pragma unroll
    for (int ks = 0; ks < 8; ks++) {
        int kc = ks * 16 + 2 * tig;
        uint32_t ahi[2][4], alo[2][4];
        #pragma unroll
        for (int mt = 0; mt < 2; mt++) {
            int rb = rbase + mt * 16 + g;
            const __nv_bfloat16* ph = sAhi + (uint32_t)rb * PADK + kc;
            const __nv_bfloat16* pl = sAlo + (uint32_t)rb * PADK + kc;
            ahi[mt][0] = *(const uint32_t*)(ph);
            ahi[mt][1] = *(const uint32_t*)(ph + 8 * PADK);
            ahi[mt][2] = *(const uint32_t*)(ph + 8);
            ahi[mt][3] = *(const uint32_t*)(ph + 8 * PADK + 8);
            alo[mt][0] = *(const uint32_t*)(pl);
            alo[mt][1] = *(const uint32_t*)(pl + 8 * PADK);
            alo[mt][2] = *(const uint32_t*)(pl + 8);
            alo[mt][3] = *(const uint32_t*)(pl + 8 * PADK + 8);
        }
        #pragma unroll
        for (int h = 0; h < 2; h++) {
            uint2 bh[4], bl[4];
            #pragma unroll
            for (int j = 0; j < 4; j++) {
                int ntg = warp_n * 8 + h * 4 + j;
                const uint2* bp = Bfrag + ((size_t)(ks * 16 + ntg) * 2) * 32 + lane;
                bh[j] = __ldg(bp);
                bl[j] = __ldg(bp + 32);
            }
            #pragma unroll
            for (int j = 0; j < 4; j++) {
                int nt = h * 4 + j;
                #pragma unroll
                for (int mt = 0; mt < 2; mt++) {
                    float* c = acc[mt][nt];
                    mma_bf16(c[0], c[1], c[2], c[3],
                             ahi[mt][0], ahi[mt][1], ahi[mt][2], ahi[mt][3], bh[j].x, bh[j].y);
                    mma_bf16(c[0], c[1], c[2], c[3],
                             ahi[mt][0], ahi[mt][1], ahi[mt][2], ahi[mt][3], bl[j].x, bl[j].y);
                    mma_bf16(c[0], c[1], c[2], c[3],
                             alo[mt][0], alo[mt][1], alo[mt][2], alo[mt][3], bh[j].x, bh[j].y);
                }
            }
        }
    }

    // ---- epilogue: bias + relu (+ norm_src fold), write hout ----
    #pragma unroll
    for (int mt = 0; mt < 2; mt++) {
        int ra = row0 + rbase + mt * 16 + g;
        int rb = ra + 8;
        bool va = ra < N_NODES, vb = rb < N_NODES;
        float nsa = 1.f, nsb = 1.f;
        if (write_mode == 0) {
            if (va) nsa = g_norm_src[ra];
            if (vb) nsb = g_norm_src[rb];
        }
        float* da = hout + (size_t)ra * DIM;
        float* db = hout + (size_t)rb * DIM;
        #pragma unroll
        for (int nt = 0; nt < 8; nt++) {
            int col = warp_n * 64 + nt * 8 + 2 * tig;
            float2 b2 = __ldg((const float2*)(bias + col));
            float* c = acc[mt][nt];
            if (va) {
                float2 o;
                o.x = fmaxf(c[0] + b2.x, 0.f) * nsa;
                o.y = fmaxf(c[1] + b2.y, 0.f) * nsa;
                *(float2*)(da + col) = o;
            }
            if (vb) {
                float2 o;
                o.x = fmaxf(c[2] + b2.x, 0.f) * nsb;
                o.y = fmaxf(c[3] + b2.y, 0.f) * nsb;
                *(float2*)(db + col) = o;
            }
        }
    }
}

// ---------------- launcher ----------------
extern "C" void kernel_launch(void* const* d_in, const int* in_sizes, int n_in,
                              void* d_out, int out_size) {
    const int*   batch = (const int*)  d_in[0];
    const int*   src   = (const int*)  d_in[1];
    const int*   dst   = (const int*)  d_in[2];
    const float* emb   = (const float*)d_in[3];
    const float* W1    = (const float*)d_in[4];
    const float* b1    = (const float*)d_in[5];
    const float* W2    = (const float*)d_in[6];
    const float* b2    = (const float*)d_in[7];
    const float* W3    = (const float*)d_in[8];
    const float* b3    = (const float*)d_in[9];
    float* out = (float*)d_out;
    (void)in_sizes; (void)n_in; (void)out_size;

    cudaFuncSetAttribute(mma_gemm_kernel, cudaFuncAttributeMaxDynamicSharedMemorySize, GEMM_SMEM);

    void* bf_ptr = nullptr;  cudaGetSymbolAddress(&bf_ptr, g_Bfrag);
    void* hs_ptr = nullptr;  cudaGetSymbolAddress(&hs_ptr, g_hs);
    void* hs2_ptr = nullptr; cudaGetSymbolAddress(&hs2_ptr, g_hs2);
    const uint2* Bf = (const uint2*)bf_ptr;
    float* hs  = (float*)hs_ptr;
    float* hs2 = (float*)hs2_ptr;
    const size_t BF_LAYER = 8 * 16 * 2 * 32;

    // degrees + norms + W fragment images
    zero_deg_kernel<<<(2 * N_NODES + 255) / 256, 256>>>();
    count_deg_kernel<<<(N_EDGES + 255) / 256, 256>>>(src, dst);
    norms_kernel<<<(N_NODES + 255) / 256, 256>>>();
    build_Bfrag_kernel<<<(3 * 8 * 16 * 32 + 255) / 256, 256>>>(W1, W2, W3);

    // CSR by dst
    scan_block_kernel<<<NB, SCAN_BLK>>>();
    scan_tops_kernel<<<1, 32>>>();
    scan_add_kernel<<<NB, SCAN_BLK>>>();
    cursor_kernel<<<(N_NODES + 255) / 256, 256>>>();
    fill_csr_kernel<<<(N_EDGES + 255) / 256, 256>>>(src, dst);

    // x = emb[batch] * norm_src -> hs
    gather_kernel<<<(N_NODES * 32 + 255) / 256, 256>>>(batch, emb);

    const int agg_blocks = (N_NODES * 32 + 255) / 256;
    const int gemm_blocks = (N_NODES + 127) / 128;

    // layer 1: hs -> agg -> hs2
    aggregate_kernel<<<agg_blocks, 256>>>(hs);
    mma_gemm_kernel<<<gemm_blocks, 256, GEMM_SMEM>>>(hs2, b1, Bf + 0 * BF_LAYER, 0);
    // layer 2: hs2 -> agg -> hs
    aggregate_kernel<<<agg_blocks, 256>>>(hs2);
    mma_gemm_kernel<<<gemm_blocks, 256, GEMM_SMEM>>>(hs,  b2, Bf + 1 * BF_LAYER, 0);
    // layer 3: hs -> agg -> out (final, no norm_src fold)
    aggregate_kernel<<<agg_blocks, 256>>>(hs);
    mma_gemm_kernel<<<gemm_blocks, 256, GEMM_SMEM>>>(out, b3, Bf + 2 * BF_LAYER, 1);
}

// round 9
// speedup vs baseline: 2.3898x; 1.0481x over previous
#include <cuda_runtime.h>
#include <cuda_bf16.h>
#include <cstdint>

#define N_NODES 50000
#define N_EDGES 800000
#define DIM 128
#define SCAN_BLK 512
#define NB ((N_NODES + SCAN_BLK - 1) / SCAN_BLK)   // 98

// ---------------- device scratch (static, allocation-free, zero-initialized) ----
__device__ float g_hs[(size_t)N_NODES * DIM];     // feature ping buffer
__device__ float g_hs2[(size_t)N_NODES * DIM];    // feature pong buffer
__device__ float g_agg[(size_t)N_NODES * DIM];    // normalized aggregate (agg * norm_dst)
__device__ float g_norm_src[N_NODES];
__device__ float g_norm_dst[N_NODES];
__device__ int   g_deg[2 * N_NODES];              // [0,N) out-deg, [N,2N) in-deg
__device__ int   g_row_ptr[N_NODES + 1];          // CSR by dst
__device__ int   g_cursor[N_NODES];
__device__ int   g_blocksum[NB];
__device__ int   g_csr_src[N_EDGES];
// W fragment images: [layer][kstep(8)][ntile(16)][img(2)][lane(32)] of uint2
__device__ uint2 g_Bfrag[3 * 8 * 16 * 2 * 32];

// ---------------- prep kernels ----------------
__global__ void zero_deg_kernel() {
    int i = blockIdx.x * blockDim.x + threadIdx.x;
    if (i < 2 * N_NODES) g_deg[i] = 0;
}
__global__ void count_deg_kernel(const int* __restrict__ src, const int* __restrict__ dst) {
    int e = blockIdx.x * blockDim.x + threadIdx.x;
    if (e < N_EDGES) {
        atomicAdd(&g_deg[src[e]], 1);
        atomicAdd(&g_deg[N_NODES + dst[e]], 1);
    }
}
__global__ void norms_kernel() {
    int i = blockIdx.x * blockDim.x + threadIdx.x;
    if (i < N_NODES) {
        g_norm_src[i] = rsqrtf((float)max(g_deg[i], 1));
        g_norm_dst[i] = rsqrtf((float)max(g_deg[N_NODES + i], 1));
    }
}

// ---- CSR build: block scan of in-degrees -> row_ptr; atomic-cursor fill ----
__global__ void scan_block_kernel() {
    __shared__ int sdata[SCAN_BLK];
    int i = blockIdx.x * SCAN_BLK + threadIdx.x;
    int v = (i < N_NODES) ? g_deg[N_NODES + i] : 0;
    sdata[threadIdx.x] = v;
    __syncthreads();
    for (int off = 1; off < SCAN_BLK; off <<= 1) {
        int t = (threadIdx.x >= off) ? sdata[threadIdx.x - off] : 0;
        __syncthreads();
        sdata[threadIdx.x] += t;
        __syncthreads();
    }
    if (i < N_NODES) g_row_ptr[i + 1] = sdata[threadIdx.x];
    if (threadIdx.x == SCAN_BLK - 1) g_blocksum[blockIdx.x] = sdata[SCAN_BLK - 1];
}
__global__ void scan_tops_kernel() {
    if (threadIdx.x == 0) {
        int acc = 0;
        for (int b = 0; b < NB; b++) { int t = g_blocksum[b]; g_blocksum[b] = acc; acc += t; }
    }
}
// finalizes row_ptr AND seeds cursor (cursor_kernel folded in)
__global__ void scan_add_kernel() {
    int i = blockIdx.x * SCAN_BLK + threadIdx.x;
    if (i < N_NODES) {
        int v = g_row_ptr[i + 1] + g_blocksum[i >> 9];
        g_row_ptr[i + 1] = v;
        if (i + 1 < N_NODES) g_cursor[i + 1] = v;
    }
    if (i == 0) { g_row_ptr[0] = 0; g_cursor[0] = 0; }
}
__global__ void fill_csr_kernel(const int* __restrict__ src, const int* __restrict__ dst) {
    int e = blockIdx.x * blockDim.x + threadIdx.x;
    if (e < N_EDGES) {
        int pos = atomicAdd(&g_cursor[dst[e]], 1);
        g_csr_src[pos] = src[e];
    }
}

__device__ __forceinline__ void bf16_split(float v, __nv_bfloat16& hi, __nv_bfloat16& lo) {
    hi = __float2bfloat16_rn(v);
    lo = __float2bfloat16_rn(v - __bfloat162float(hi));
}
__device__ __forceinline__ uint32_t pack2(__nv_bfloat16 a, __nv_bfloat16 b) {
    __nv_bfloat162 p = __halves2bfloat162(a, b);
    return *(uint32_t*)&p;
}

// B fragment images for mma.m16n8k16 .col B
__global__ void build_Bfrag_kernel(const float* __restrict__ W1, const float* __restrict__ W2,
                                   const float* __restrict__ W3) {
    int t = blockIdx.x * blockDim.x + threadIdx.x;
    if (t >= 3 * 8 * 16 * 32) return;
    int layer = t >> 12;
    int rem = t & 4095;
    int ks = rem >> 9;
    int nt = (rem >> 5) & 15;
    int lane = rem & 31;
    int g = lane >> 2, tig = lane & 3;
    const float* W = (layer == 0) ? W1 : (layer == 1) ? W2 : W3;
    int n = nt * 8 + g;
    int k0 = ks * 16 + 2 * tig;
    float w00 = W[(k0 + 0) * DIM + n];
    float w01 = W[(k0 + 1) * DIM + n];
    float w10 = W[(k0 + 8) * DIM + n];
    float w11 = W[(k0 + 9) * DIM + n];
    __nv_bfloat16 h00, l00, h01, l01, h10, l10, h11, l11;
    bf16_split(w00, h00, l00); bf16_split(w01, h01, l01);
    bf16_split(w10, h10, l10); bf16_split(w11, h11, l11);
    int idx = (layer * 8 + ks) * 16 + nt;
    g_Bfrag[(idx * 2 + 0) * 32 + lane] = make_uint2(pack2(h00, h01), pack2(h10, h11));
    g_Bfrag[(idx * 2 + 1) * 32 + lane] = make_uint2(pack2(l00, l01), pack2(l10, l11));
}

// ---------------- aggregation kernels ----------------
// Layer 1: g_agg[r] = norm_dst[r] * sum_e emb[batch[src_e]] * norm_src[src_e]
// (embedding gather fused; g_hs never materialized)
__global__ __launch_bounds__(256)
void aggregate_emb_kernel(const int* __restrict__ batch, const float* __restrict__ emb) {
    int t = blockIdx.x * blockDim.x + threadIdx.x;
    int gr = t >> 5;
    int lane = t & 31;
    if (gr >= N_NODES) return;

    int beg = __ldg(g_row_ptr + gr);
    int end = __ldg(g_row_ptr + gr + 1);
    float ax = 0.f, ay = 0.f, az = 0.f, aw = 0.f;
    int j = beg;
    for (; j + 3 < end; j += 4) {
        int s0 = __ldg(g_csr_src + j);
        int s1 = __ldg(g_csr_src + j + 1);
        int s2 = __ldg(g_csr_src + j + 2);
        int s3 = __ldg(g_csr_src + j + 3);
        int b0 = __ldg(batch + s0), b1 = __ldg(batch + s1);
        int b2 = __ldg(batch + s2), b3 = __ldg(batch + s3);
        float n0 = __ldg(g_norm_src + s0), n1 = __ldg(g_norm_src + s1);
        float n2 = __ldg(g_norm_src + s2), n3 = __ldg(g_norm_src + s3);
        float4 v0 = __ldg((const float4*)(emb + (size_t)b0 * DIM) + lane);
        float4 v1 = __ldg((const float4*)(emb + (size_t)b1 * DIM) + lane);
        float4 v2 = __ldg((const float4*)(emb + (size_t)b2 * DIM) + lane);
        float4 v3 = __ldg((const float4*)(emb + (size_t)b3 * DIM) + lane);
        ax += v0.x * n0; ay += v0.y * n0; az += v0.z * n0; aw += v0.w * n0;
        ax += v1.x * n1; ay += v1.y * n1; az += v1.z * n1; aw += v1.w * n1;
        ax += v2.x * n2; ay += v2.y * n2; az += v2.z * n2; aw += v2.w * n2;
        ax += v3.x * n3; ay += v3.y * n3; az += v3.z * n3; aw += v3.w * n3;
    }
    for (; j < end; j++) {
        int s0 = __ldg(g_csr_src + j);
        int b0 = __ldg(batch + s0);
        float n0 = __ldg(g_norm_src + s0);
        float4 v0 = __ldg((const float4*)(emb + (size_t)b0 * DIM) + lane);
        ax += v0.x * n0; ay += v0.y * n0; az += v0.z * n0; aw += v0.w * n0;
    }
    float nd = __ldg(g_norm_dst + gr);
    ((float4*)(g_agg + (size_t)gr * DIM))[lane] = make_float4(ax * nd, ay * nd, az * nd, aw * nd);
}

// Layers 2-3: g_agg[r] = norm_dst[r] * sum_e hin[src_e]
__global__ __launch_bounds__(256)
void aggregate_kernel(const float* __restrict__ hin) {
    int t = blockIdx.x * blockDim.x + threadIdx.x;
    int gr = t >> 5;
    int lane = t & 31;
    if (gr >= N_NODES) return;

    int beg = __ldg(g_row_ptr + gr);
    int end = __ldg(g_row_ptr + gr + 1);
    float ax = 0.f, ay = 0.f, az = 0.f, aw = 0.f;
    int j = beg;
    for (; j + 3 < end; j += 4) {
        int s0 = __ldg(g_csr_src + j);
        int s1 = __ldg(g_csr_src + j + 1);
        int s2 = __ldg(g_csr_src + j + 2);
        int s3 = __ldg(g_csr_src + j + 3);
        float4 v0 = __ldg((const float4*)(hin + (size_t)s0 * DIM) + lane);
        float4 v1 = __ldg((const float4*)(hin + (size_t)s1 * DIM) + lane);
        float4 v2 = __ldg((const float4*)(hin + (size_t)s2 * DIM) + lane);
        float4 v3 = __ldg((const float4*)(hin + (size_t)s3 * DIM) + lane);
        ax += v0.x; ay += v0.y; az += v0.z; aw += v0.w;
        ax += v1.x; ay += v1.y; az += v1.z; aw += v1.w;
        ax += v2.x; ay += v2.y; az += v2.z; aw += v2.w;
        ax += v3.x; ay += v3.y; az += v3.z; aw += v3.w;
    }
    for (; j < end; j++) {
        int s0 = __ldg(g_csr_src + j);
        float4 v0 = __ldg((const float4*)(hin + (size_t)s0 * DIM) + lane);
        ax += v0.x; ay += v0.y; az += v0.z; aw += v0.w;
    }
    float nd = __ldg(g_norm_dst + gr);
    ((float4*)(g_agg + (size_t)gr * DIM))[lane] = make_float4(ax * nd, ay * nd, az * nd, aw * nd);
}

// ---------------- bf16-split mma GEMM: hout = relu(g_agg @ W + b) [* norm_src] ----
#define PADK 136
#define A_IMG_BYTES (128 * PADK * 2)
#define GEMM_SMEM (2 * A_IMG_BYTES)

__device__ __forceinline__ void mma_bf16(float& c0, float& c1, float& c2, float& c3,
                                         uint32_t a0, uint32_t a1, uint32_t a2, uint32_t a3,
                                         uint32_t b0, uint32_t b1) {
    asm volatile(
        "mma.sync.aligned.m16n8k16.row.col.f32.bf16.bf16.f32 "
        "{%0,%1,%2,%3}, {%4,%5,%6,%7}, {%8,%9}, {%0,%1,%2,%3};"
        : "+f"(c0), "+f"(c1), "+f"(c2), "+f"(c3)
        : "r"(a0), "r"(a1), "r"(a2), "r"(a3), "r"(b0), "r"(b1));
}

__global__ __launch_bounds__(256, 2)
void mma_gemm_kernel(float* __restrict__ hout, const float* __restrict__ bias,
                     const uint2* __restrict__ Bfrag, int write_mode) {
    extern __shared__ char smem[];
    __nv_bfloat16* sAhi = (__nv_bfloat16*)smem;
    __nv_bfloat16* sAlo = (__nv_bfloat16*)(smem + A_IMG_BYTES);

    int tid = threadIdx.x;
    int wid = tid >> 5, lane = tid & 31;
    int warp_m = wid >> 1, warp_n = wid & 1;
    int g = lane >> 2, tig = lane & 3;
    int row0 = blockIdx.x * 128;

    // ---- load A tile (coalesced stream from g_agg), bf16 split into smem ----
    #pragma unroll
    for (int it = 0; it < 16; it++) {
        int i = tid + it * 256;           // 0..4095 float4 chunks
        int r = i >> 5, c4 = i & 31;
        int gr = row0 + r;
        float4 v = make_float4(0.f, 0.f, 0.f, 0.f);
        if (gr < N_NODES)
            v = ((const float4*)(g_agg + (size_t)gr * DIM))[c4];
        __nv_bfloat16 h0, l0, h1, l1, h2, l2, h3, l3;
        bf16_split(v.x, h0, l0); bf16_split(v.y, h1, l1);
        bf16_split(v.z, h2, l2); bf16_split(v.w, h3, l3);
        uint32_t off = (uint32_t)r * PADK + (uint32_t)c4 * 4;
        *(uint2*)(sAhi + off) = make_uint2(pack2(h0, h1), pack2(h2, h3));
        *(uint2*)(sAlo + off) = make_uint2(pack2(l0, l1), pack2(l2, l3));
    }
    __syncthreads();

    // ---- MMA ----
    float acc[2][8][4];
    #pragma unroll
    for (int mt = 0; mt < 2; mt++)
        #pragma unroll
        for (int nt = 0; nt < 8; nt++)
            #pragma unroll
            for (int q = 0; q < 4; q++) acc[mt][nt][q] = 0.f;

    const int rbase = warp_m * 32;
    #pragma unroll
    for (int ks = 0; ks < 8; ks++) {
        int kc = ks * 16 + 2 * tig;
        uint32_t ahi[2][4], alo[2][4];
        #pragma unroll
        for (int mt = 0; mt < 2; mt++) {
            int rb = rbase + mt * 16 + g;
            const __nv_bfloat16* ph = sAhi + (uint32_t)rb * PADK + kc;
            const __nv_bfloat16* pl = sAlo + (uint32_t)rb * PADK + kc;
            ahi[mt][0] = *(const uint32_t*)(ph);
            ahi[mt][1] = *(const uint32_t*)(ph + 8 * PADK);
            ahi[mt][2] = *(const uint32_t*)(ph + 8);
            ahi[mt][3] = *(const uint32_t*)(ph + 8 * PADK + 8);
            alo[mt][0] = *(const uint32_t*)(pl);
            alo[mt][1] = *(const uint32_t*)(pl + 8 * PADK);
            alo[mt][2] = *(const uint32_t*)(pl + 8);
            alo[mt][3] = *(const uint32_t*)(pl + 8 * PADK + 8);
        }
        #pragma unroll
        for (int h = 0; h < 2; h++) {
            uint2 bh[4], bl[4];
            #pragma unroll
            for (int j = 0; j < 4; j++) {
                int ntg = warp_n * 8 + h * 4 + j;
                const uint2* bp = Bfrag + ((size_t)(ks * 16 + ntg) * 2) * 32 + lane;
                bh[j] = __ldg(bp);
                bl[j] = __ldg(bp + 32);
            }
            #pragma unroll
            for (int j = 0; j < 4; j++) {
                int nt = h * 4 + j;
                #pragma unroll
                for (int mt = 0; mt < 2; mt++) {
                    float* c = acc[mt][nt];
                    mma_bf16(c[0], c[1], c[2], c[3],
                             ahi[mt][0], ahi[mt][1], ahi[mt][2], ahi[mt][3], bh[j].x, bh[j].y);
                    mma_bf16(c[0], c[1], c[2], c[3],
                             ahi[mt][0], ahi[mt][1], ahi[mt][2], ahi[mt][3], bl[j].x, bl[j].y);
                    mma_bf16(c[0], c[1], c[2], c[3],
                             alo[mt][0], alo[mt][1], alo[mt][2], alo[mt][3], bh[j].x, bh[j].y);
                }
            }
        }
    }

    // ---- epilogue: bias + relu (+ norm_src fold), write hout ----
    #pragma unroll
    for (int mt = 0; mt < 2; mt++) {
        int ra = row0 + rbase + mt * 16 + g;
        int rb = ra + 8;
        bool va = ra < N_NODES, vb = rb < N_NODES;
        float nsa = 1.f, nsb = 1.f;
        if (write_mode == 0) {
            if (va) nsa = g_norm_src[ra];
            if (vb) nsb = g_norm_src[rb];
        }
        float* da = hout + (size_t)ra * DIM;
        float* db = hout + (size_t)rb * DIM;
        #pragma unroll
        for (int nt = 0; nt < 8; nt++) {
            int col = warp_n * 64 + nt * 8 + 2 * tig;
            float2 b2 = __ldg((const float2*)(bias + col));
            float* c = acc[mt][nt];
            if (va) {
                float2 o;
                o.x = fmaxf(c[0] + b2.x, 0.f) * nsa;
                o.y = fmaxf(c[1] + b2.y, 0.f) * nsa;
                *(float2*)(da + col) = o;
            }
            if (vb) {
                float2 o;
                o.x = fmaxf(c[2] + b2.x, 0.f) * nsb;
                o.y = fmaxf(c[3] + b2.y, 0.f) * nsb;
                *(float2*)(db + col) = o;
            }
        }
    }
}

// ---------------- launcher ----------------
extern "C" void kernel_launch(void* const* d_in, const int* in_sizes, int n_in,
                              void* d_out, int out_size) {
    const int*   batch = (const int*)  d_in[0];
    const int*   src   = (const int*)  d_in[1];
    const int*   dst   = (const int*)  d_in[2];
    const float* emb   = (const float*)d_in[3];
    const float* W1    = (const float*)d_in[4];
    const float* b1    = (const float*)d_in[5];
    const float* W2    = (const float*)d_in[6];
    const float* b2    = (const float*)d_in[7];
    const float* W3    = (const float*)d_in[8];
    const float* b3    = (const float*)d_in[9];
    float* out = (float*)d_out;
    (void)in_sizes; (void)n_in; (void)out_size;

    cudaFuncSetAttribute(mma_gemm_kernel, cudaFuncAttributeMaxDynamicSharedMemorySize, GEMM_SMEM);

    void* bf_ptr = nullptr;  cudaGetSymbolAddress(&bf_ptr, g_Bfrag);
    void* hs_ptr = nullptr;  cudaGetSymbolAddress(&hs_ptr, g_hs);
    void* hs2_ptr = nullptr; cudaGetSymbolAddress(&hs2_ptr, g_hs2);
    const uint2* Bf = (const uint2*)bf_ptr;
    float* hs  = (float*)hs_ptr;
    float* hs2 = (float*)hs2_ptr;
    const size_t BF_LAYER = 8 * 16 * 2 * 32;

    // degrees + norms + W fragment images
    zero_deg_kernel<<<(2 * N_NODES + 255) / 256, 256>>>();
    count_deg_kernel<<<(N_EDGES + 255) / 256, 256>>>(src, dst);
    norms_kernel<<<(N_NODES + 255) / 256, 256>>>();
    build_Bfrag_kernel<<<(3 * 8 * 16 * 32 + 255) / 256, 256>>>(W1, W2, W3);

    // CSR by dst (cursor seeded inside scan_add)
    scan_block_kernel<<<NB, SCAN_BLK>>>();
    scan_tops_kernel<<<1, 32>>>();
    scan_add_kernel<<<NB, SCAN_BLK>>>();
    fill_csr_kernel<<<(N_EDGES + 255) / 256, 256>>>(src, dst);

    const int agg_blocks = (N_NODES * 32 + 255) / 256;
    const int gemm_blocks = (N_NODES + 127) / 128;

    // layer 1: (emb, batch) -> agg -> hs2   (gather fused into aggregation)
    aggregate_emb_kernel<<<agg_blocks, 256>>>(batch, emb);
    mma_gemm_kernel<<<gemm_blocks, 256, GEMM_SMEM>>>(hs2, b1, Bf + 0 * BF_LAYER, 0);
    // layer 2: hs2 -> agg -> hs
    aggregate_kernel<<<agg_blocks, 256>>>(hs2);
    mma_gemm_kernel<<<gemm_blocks, 256, GEMM_SMEM>>>(hs,  b2, Bf + 1 * BF_LAYER, 0);
    // layer 3: hs -> agg -> out (final, no norm_src fold)
    aggregate_kernel<<<agg_blocks, 256>>>(hs);
    mma_gemm_kernel<<<gemm_blocks, 256, GEMM_SMEM>>>(out, b3, Bf + 2 * BF_LAYER, 1);
}

// round 10
// speedup vs baseline: 2.4770x; 1.0365x over previous
#include <cuda_runtime.h>
#include <cuda_bf16.h>
#include <cstdint>

#define N_NODES 50000
#define N_EDGES 800000
#define DIM 128
#define SCAN_BLK 512
#define NB ((N_NODES + SCAN_BLK - 1) / SCAN_BLK)   // 98

// ---------------- device scratch (static, allocation-free, zero-initialized) ----
__device__ float g_hs[(size_t)N_NODES * DIM];     // feature ping buffer
__device__ float g_hs2[(size_t)N_NODES * DIM];    // feature pong buffer
__device__ float g_agg[(size_t)N_NODES * DIM];    // normalized aggregate (agg * norm_dst)
__device__ float g_norm_src[N_NODES];
__device__ float g_norm_dst[N_NODES];
__device__ int   g_deg[2 * N_NODES];              // [0,N) out-deg, [N,2N) in-deg
__device__ int   g_row_ptr[N_NODES + 1];          // CSR by dst
__device__ int   g_cursor[N_NODES];
__device__ int   g_blocksum[NB];
__device__ int   g_csr_src[N_EDGES];
// W fragment images: [layer][kstep(8)][ntile(16)][img(2)][lane(32)] of uint2
__device__ uint2 g_Bfrag[3 * 8 * 16 * 2 * 32];

// ---------------- prep kernels ----------------
__global__ void zero_deg_kernel() {
    int i = blockIdx.x * blockDim.x + threadIdx.x;
    if (i < 2 * N_NODES) g_deg[i] = 0;
}
__global__ void count_deg_kernel(const int* __restrict__ src, const int* __restrict__ dst) {
    int e = blockIdx.x * blockDim.x + threadIdx.x;
    if (e < N_EDGES) {
        atomicAdd(&g_deg[src[e]], 1);
        atomicAdd(&g_deg[N_NODES + dst[e]], 1);
    }
}
__global__ void norms_kernel() {
    int i = blockIdx.x * blockDim.x + threadIdx.x;
    if (i < N_NODES) {
        g_norm_src[i] = rsqrtf((float)max(g_deg[i], 1));
        g_norm_dst[i] = rsqrtf((float)max(g_deg[N_NODES + i], 1));
    }
}

// ---- CSR build: block scan of in-degrees -> row_ptr; atomic-cursor fill ----
__global__ void scan_block_kernel() {
    __shared__ int sdata[SCAN_BLK];
    int i = blockIdx.x * SCAN_BLK + threadIdx.x;
    int v = (i < N_NODES) ? g_deg[N_NODES + i] : 0;
    sdata[threadIdx.x] = v;
    __syncthreads();
    for (int off = 1; off < SCAN_BLK; off <<= 1) {
        int t = (threadIdx.x >= off) ? sdata[threadIdx.x - off] : 0;
        __syncthreads();
        sdata[threadIdx.x] += t;
        __syncthreads();
    }
    if (i < N_NODES) g_row_ptr[i + 1] = sdata[threadIdx.x];
    if (threadIdx.x == SCAN_BLK - 1) g_blocksum[blockIdx.x] = sdata[SCAN_BLK - 1];
}
__global__ void scan_tops_kernel() {
    if (threadIdx.x == 0) {
        int acc = 0;
        for (int b = 0; b < NB; b++) { int t = g_blocksum[b]; g_blocksum[b] = acc; acc += t; }
    }
}
// finalizes row_ptr AND seeds cursor
__global__ void scan_add_kernel() {
    int i = blockIdx.x * SCAN_BLK + threadIdx.x;
    if (i < N_NODES) {
        int v = g_row_ptr[i + 1] + g_blocksum[i >> 9];
        g_row_ptr[i + 1] = v;
        if (i + 1 < N_NODES) g_cursor[i + 1] = v;
    }
    if (i == 0) { g_row_ptr[0] = 0; g_cursor[0] = 0; }
}
__global__ void fill_csr_kernel(const int* __restrict__ src, const int* __restrict__ dst) {
    int e = blockIdx.x * blockDim.x + threadIdx.x;
    if (e < N_EDGES) {
        int pos = atomicAdd(&g_cursor[dst[e]], 1);
        g_csr_src[pos] = src[e];
    }
}

__device__ __forceinline__ void bf16_split(float v, __nv_bfloat16& hi, __nv_bfloat16& lo) {
    hi = __float2bfloat16_rn(v);
    lo = __float2bfloat16_rn(v - __bfloat162float(hi));
}
__device__ __forceinline__ uint32_t pack2(__nv_bfloat16 a, __nv_bfloat16 b) {
    __nv_bfloat162 p = __halves2bfloat162(a, b);
    return *(uint32_t*)&p;
}

// B fragment images for mma.m16n8k16 .col B
__global__ void build_Bfrag_kernel(const float* __restrict__ W1, const float* __restrict__ W2,
                                   const float* __restrict__ W3) {
    int t = blockIdx.x * blockDim.x + threadIdx.x;
    if (t >= 3 * 8 * 16 * 32) return;
    int layer = t >> 12;
    int rem = t & 4095;
    int ks = rem >> 9;
    int nt = (rem >> 5) & 15;
    int lane = rem & 31;
    int g = lane >> 2, tig = lane & 3;
    const float* W = (layer == 0) ? W1 : (layer == 1) ? W2 : W3;
    int n = nt * 8 + g;
    int k0 = ks * 16 + 2 * tig;
    float w00 = W[(k0 + 0) * DIM + n];
    float w01 = W[(k0 + 1) * DIM + n];
    float w10 = W[(k0 + 8) * DIM + n];
    float w11 = W[(k0 + 9) * DIM + n];
    __nv_bfloat16 h00, l00, h01, l01, h10, l10, h11, l11;
    bf16_split(w00, h00, l00); bf16_split(w01, h01, l01);
    bf16_split(w10, h10, l10); bf16_split(w11, h11, l11);
    int idx = (layer * 8 + ks) * 16 + nt;
    g_Bfrag[(idx * 2 + 0) * 32 + lane] = make_uint2(pack2(h00, h01), pack2(h10, h11));
    g_Bfrag[(idx * 2 + 1) * 32 + lane] = make_uint2(pack2(l00, l01), pack2(l10, l11));
}

// ---------------- aggregation kernels ----------------
// Layer 1: g_agg[r] = norm_dst[r] * sum_e emb[batch[src_e]] * norm_src[src_e]
__global__ __launch_bounds__(256)
void aggregate_emb_kernel(const int* __restrict__ batch, const float* __restrict__ emb) {
    int t = blockIdx.x * blockDim.x + threadIdx.x;
    int gr = t >> 5;
    int lane = t & 31;
    if (gr >= N_NODES) return;

    int beg = __ldg(g_row_ptr + gr);
    int end = __ldg(g_row_ptr + gr + 1);
    float ax = 0.f, ay = 0.f, az = 0.f, aw = 0.f;
    int j = beg;
    for (; j + 3 < end; j += 4) {
        int s0 = __ldg(g_csr_src + j);
        int s1 = __ldg(g_csr_src + j + 1);
        int s2 = __ldg(g_csr_src + j + 2);
        int s3 = __ldg(g_csr_src + j + 3);
        int b0 = __ldg(batch + s0), b1 = __ldg(batch + s1);
        int b2 = __ldg(batch + s2), b3 = __ldg(batch + s3);
        float n0 = __ldg(g_norm_src + s0), n1 = __ldg(g_norm_src + s1);
        float n2 = __ldg(g_norm_src + s2), n3 = __ldg(g_norm_src + s3);
        float4 v0 = __ldg((const float4*)(emb + (size_t)b0 * DIM) + lane);
        float4 v1 = __ldg((const float4*)(emb + (size_t)b1 * DIM) + lane);
        float4 v2 = __ldg((const float4*)(emb + (size_t)b2 * DIM) + lane);
        float4 v3 = __ldg((const float4*)(emb + (size_t)b3 * DIM) + lane);
        ax += v0.x * n0; ay += v0.y * n0; az += v0.z * n0; aw += v0.w * n0;
        ax += v1.x * n1; ay += v1.y * n1; az += v1.z * n1; aw += v1.w * n1;
        ax += v2.x * n2; ay += v2.y * n2; az += v2.z * n2; aw += v2.w * n2;
        ax += v3.x * n3; ay += v3.y * n3; az += v3.z * n3; aw += v3.w * n3;
    }
    for (; j < end; j++) {
        int s0 = __ldg(g_csr_src + j);
        int b0 = __ldg(batch + s0);
        float n0 = __ldg(g_norm_src + s0);
        float4 v0 = __ldg((const float4*)(emb + (size_t)b0 * DIM) + lane);
        ax += v0.x * n0; ay += v0.y * n0; az += v0.z * n0; aw += v0.w * n0;
    }
    float nd = __ldg(g_norm_dst + gr);
    ((float4*)(g_agg + (size_t)gr * DIM))[lane] = make_float4(ax * nd, ay * nd, az * nd, aw * nd);
}

// Layers 2-3: g_agg[r] = norm_dst[r] * sum_e hin[src_e]
__global__ __launch_bounds__(256)
void aggregate_kernel(const float* __restrict__ hin) {
    int t = blockIdx.x * blockDim.x + threadIdx.x;
    int gr = t >> 5;
    int lane = t & 31;
    if (gr >= N_NODES) return;

    int beg = __ldg(g_row_ptr + gr);
    int end = __ldg(g_row_ptr + gr + 1);
    float ax = 0.f, ay = 0.f, az = 0.f, aw = 0.f;
    int j = beg;
    for (; j + 3 < end; j += 4) {
        int s0 = __ldg(g_csr_src + j);
        int s1 = __ldg(g_csr_src + j + 1);
        int s2 = __ldg(g_csr_src + j + 2);
        int s3 = __ldg(g_csr_src + j + 3);
        float4 v0 = __ldg((const float4*)(hin + (size_t)s0 * DIM) + lane);
        float4 v1 = __ldg((const float4*)(hin + (size_t)s1 * DIM) + lane);
        float4 v2 = __ldg((const float4*)(hin + (size_t)s2 * DIM) + lane);
        float4 v3 = __ldg((const float4*)(hin + (size_t)s3 * DIM) + lane);
        ax += v0.x; ay += v0.y; az += v0.z; aw += v0.w;
        ax += v1.x; ay += v1.y; az += v1.z; aw += v1.w;
        ax += v2.x; ay += v2.y; az += v2.z; aw += v2.w;
        ax += v3.x; ay += v3.y; az += v3.z; aw += v3.w;
    }
    for (; j < end; j++) {
        int s0 = __ldg(g_csr_src + j);
        float4 v0 = __ldg((const float4*)(hin + (size_t)s0 * DIM) + lane);
        ax += v0.x; ay += v0.y; az += v0.z; aw += v0.w;
    }
    float nd = __ldg(g_norm_dst + gr);
    ((float4*)(g_agg + (size_t)gr * DIM))[lane] = make_float4(ax * nd, ay * nd, az * nd, aw * nd);
}

// ---------------- bf16-split mma GEMM: hout = relu(g_agg @ W + b) [* norm_src] ----
// 512 threads, 4x4 warp grid, warp tile 32x32 -> ~85 regs, true 2 CTAs/SM.
#define PADK 136
#define A_IMG_BYTES (128 * PADK * 2)
#define GEMM_SMEM (2 * A_IMG_BYTES)

__device__ __forceinline__ void mma_bf16(float& c0, float& c1, float& c2, float& c3,
                                         uint32_t a0, uint32_t a1, uint32_t a2, uint32_t a3,
                                         uint32_t b0, uint32_t b1) {
    asm volatile(
        "mma.sync.aligned.m16n8k16.row.col.f32.bf16.bf16.f32 "
        "{%0,%1,%2,%3}, {%4,%5,%6,%7}, {%8,%9}, {%0,%1,%2,%3};"
        : "+f"(c0), "+f"(c1), "+f"(c2), "+f"(c3)
        : "r"(a0), "r"(a1), "r"(a2), "r"(a3), "r"(b0), "r"(b1));
}

__global__ __launch_bounds__(512, 2)
void mma_gemm_kernel(float* __restrict__ hout, const float* __restrict__ bias,
                     const uint2* __restrict__ Bfrag, int write_mode) {
    extern __shared__ char smem[];
    __nv_bfloat16* sAhi = (__nv_bfloat16*)smem;
    __nv_bfloat16* sAlo = (__nv_bfloat16*)(smem + A_IMG_BYTES);

    int tid = threadIdx.x;
    int wid = tid >> 5, lane = tid & 31;
    int warp_m = wid >> 2, warp_n = wid & 3;      // 4x4 warp grid
    int g = lane >> 2, tig = lane & 3;
    int row0 = blockIdx.x * 128;

    // ---- load A tile (coalesced stream from g_agg), bf16 split into smem ----
    #pragma unroll
    for (int it = 0; it < 8; it++) {
        int i = tid + it * 512;           // 0..4095 float4 chunks
        int r = i >> 5, c4 = i & 31;
        int gr = row0 + r;
        float4 v = make_float4(0.f, 0.f, 0.f, 0.f);
        if (gr < N_NODES)
            v = ((const float4*)(g_agg + (size_t)gr * DIM))[c4];
        __nv_bfloat16 h0, l0, h1, l1, h2, l2, h3, l3;
        bf16_split(v.x, h0, l0); bf16_split(v.y, h1, l1);
        bf16_split(v.z, h2, l2); bf16_split(v.w, h3, l3);
        uint32_t off = (uint32_t)r * PADK + (uint32_t)c4 * 4;
        *(uint2*)(sAhi + off) = make_uint2(pack2(h0, h1), pack2(h2, h3));
        *(uint2*)(sAlo + off) = make_uint2(pack2(l0, l1), pack2(l2, l3));
    }
    __syncthreads();

    // ---- MMA: warp tile 32 rows x 32 cols ----
    float acc[2][4][4];
    #pragma unroll
    for (int mt = 0; mt < 2; mt++)
        #pragma unroll
        for (int nt = 0; nt < 4; nt++)
            #pragma unroll
            for (int q = 0; q < 4; q++) acc[mt][nt][q] = 0.f;

    const int rbase = warp_m * 32;
    #pragma unroll
    for (int ks = 0; ks < 8; ks++) {
        int kc = ks * 16 + 2 * tig;
        uint32_t ahi[2][4], alo[2][4];
        #pragma unroll
        for (int mt = 0; mt < 2; mt++) {
            int rb = rbase + mt * 16 + g;
            const __nv_bfloat16* ph = sAhi + (uint32_t)rb * PADK + kc;
            const __nv_bfloat16* pl = sAlo + (uint32_t)rb * PADK + kc;
            ahi[mt][0] = *(const uint32_t*)(ph);
            ahi[mt][1] = *(const uint32_t*)(ph + 8 * PADK);
            ahi[mt][2] = *(const uint32_t*)(ph + 8);
            ahi[mt][3] = *(const uint32_t*)(ph + 8 * PADK + 8);
            alo[mt][0] = *(const uint32_t*)(pl);
            alo[mt][1] = *(const uint32_t*)(pl + 8 * PADK);
            alo[mt][2] = *(const uint32_t*)(pl + 8);
            alo[mt][3] = *(const uint32_t*)(pl + 8 * PADK + 8);
        }
        uint2 bh[4], bl[4];
        #pragma unroll
        for (int j = 0; j < 4; j++) {
            int ntg = warp_n * 4 + j;
            const uint2* bp = Bfrag + ((size_t)(ks * 16 + ntg) * 2) * 32 + lane;
            bh[j] = __ldg(bp);
            bl[j] = __ldg(bp + 32);
        }
        #pragma unroll
        for (int j = 0; j < 4; j++) {
            #pragma unroll
            for (int mt = 0; mt < 2; mt++) {
                float* c = acc[mt][j];
                mma_bf16(c[0], c[1], c[2], c[3],
                         ahi[mt][0], ahi[mt][1], ahi[mt][2], ahi[mt][3], bh[j].x, bh[j].y);
                mma_bf16(c[0], c[1], c[2], c[3],
                         ahi[mt][0], ahi[mt][1], ahi[mt][2], ahi[mt][3], bl[j].x, bl[j].y);
                mma_bf16(c[0], c[1], c[2], c[3],
                         alo[mt][0], alo[mt][1], alo[mt][2], alo[mt][3], bh[j].x, bh[j].y);
            }
        }
    }

    // ---- epilogue: bias + relu (+ norm_src fold), write hout ----
    #pragma unroll
    for (int mt = 0; mt < 2; mt++) {
        int ra = row0 + rbase + mt * 16 + g;
        int rb = ra + 8;
        bool va = ra < N_NODES, vb = rb < N_NODES;
        float nsa = 1.f, nsb = 1.f;
        if (write_mode == 0) {
            if (va) nsa = g_norm_src[ra];
            if (vb) nsb = g_norm_src[rb];
        }
        float* da = hout + (size_t)ra * DIM;
        float* db = hout + (size_t)rb * DIM;
        #pragma unroll
        for (int nt = 0; nt < 4; nt++) {
            int col = warp_n * 32 + nt * 8 + 2 * tig;
            float2 b2 = __ldg((const float2*)(bias + col));
            float* c = acc[mt][nt];
            if (va) {
                float2 o;
                o.x = fmaxf(c[0] + b2.x, 0.f) * nsa;
                o.y = fmaxf(c[1] + b2.y, 0.f) * nsa;
                *(float2*)(da + col) = o;
            }
            if (vb) {
                float2 o;
                o.x = fmaxf(c[2] + b2.x, 0.f) * nsb;
                o.y = fmaxf(c[3] + b2.y, 0.f) * nsb;
                *(float2*)(db + col) = o;
            }
        }
    }
}

// ---------------- launcher ----------------
extern "C" void kernel_launch(void* const* d_in, const int* in_sizes, int n_in,
                              void* d_out, int out_size) {
    const int*   batch = (const int*)  d_in[0];
    const int*   src   = (const int*)  d_in[1];
    const int*   dst   = (const int*)  d_in[2];
    const float* emb   = (const float*)d_in[3];
    const float* W1    = (const float*)d_in[4];
    const float* b1    = (const float*)d_in[5];
    const float* W2    = (const float*)d_in[6];
    const float* b2    = (const float*)d_in[7];
    const float* W3    = (const float*)d_in[8];
    const float* b3    = (const float*)d_in[9];
    float* out = (float*)d_out;
    (void)in_sizes; (void)n_in; (void)out_size;

    cudaFuncSetAttribute(mma_gemm_kernel, cudaFuncAttributeMaxDynamicSharedMemorySize, GEMM_SMEM);

    void* bf_ptr = nullptr;  cudaGetSymbolAddress(&bf_ptr, g_Bfrag);
    void* hs_ptr = nullptr;  cudaGetSymbolAddress(&hs_ptr, g_hs);
    void* hs2_ptr = nullptr; cudaGetSymbolAddress(&hs2_ptr, g_hs2);
    const uint2* Bf = (const uint2*)bf_ptr;
    float* hs  = (float*)hs_ptr;
    float* hs2 = (float*)hs2_ptr;
    const size_t BF_LAYER = 8 * 16 * 2 * 32;

    // degrees + norms + W fragment images
    zero_deg_kernel<<<(2 * N_NODES + 255) / 256, 256>>>();
    count_deg_kernel<<<(N_EDGES + 255) / 256, 256>>>(src, dst);
    norms_kernel<<<(N_NODES + 255) / 256, 256>>>();
    build_Bfrag_kernel<<<(3 * 8 * 16 * 32 + 255) / 256, 256>>>(W1, W2, W3);

    // CSR by dst (cursor seeded inside scan_add)
    scan_block_kernel<<<NB, SCAN_BLK>>>();
    scan_tops_kernel<<<1, 32>>>();
    scan_add_kernel<<<NB, SCAN_BLK>>>();
    fill_csr_kernel<<<(N_EDGES + 255) / 256, 256>>>(src, dst);

    const int agg_blocks = (N_NODES * 32 + 255) / 256;
    const int gemm_blocks = (N_NODES + 127) / 128;

    // layer 1: (emb, batch) -> agg -> hs2   (gather fused into aggregation)
    aggregate_emb_kernel<<<agg_blocks, 256>>>(batch, emb);
    mma_gemm_kernel<<<gemm_blocks, 512, GEMM_SMEM>>>(hs2, b1, Bf + 0 * BF_LAYER, 0);
    // layer 2: hs2 -> agg -> hs
    aggregate_kernel<<<agg_blocks, 256>>>(hs2);
    mma_gemm_kernel<<<gemm_blocks, 512, GEMM_SMEM>>>(hs,  b2, Bf + 1 * BF_LAYER, 0);
    // layer 3: hs -> agg -> out (final, no norm_src fold)
    aggregate_kernel<<<agg_blocks, 256>>>(hs);
    mma_gemm_kernel<<<gemm_blocks, 512, GEMM_SMEM>>>(out, b3, Bf + 2 * BF_LAYER, 1);
}